// round 5
// baseline (speedup 1.0000x reference)
#include <cuda_runtime.h>
#include <cuda.h>
#include <cuda_fp16.h>
#include <cstdint>
#include <cstddef>
#include <cstring>

// ----------------------------- problem sizes ------------------------------
#define BB 4096   // batch
#define DD 1024   // input dim
#define HH 4096   // hidden dim
#define NSTEPS 64

// ------------------------------ GEMM tiling -------------------------------
#define BM 128
#define BN 128
#define BK 64                 // fp16 elements per K-chunk = 128 bytes (SW128 atom)
#define STAGES 4
#define TILE_BYTES 16384      // 128 rows * 128 B
#define CHUNK_BYTES (3*TILE_BYTES)   // A + B_hi + B_lo
#define SMEM_REQ (STAGES*CHUNK_BYTES + 2048)

#define LO_SCALE 1024.0f
#define LO_INV   (1.0f/1024.0f)

// idesc: dtype=F32(1<<4), atype=F16(0), btype=F16(0), N=128 ((128/8)<<17), M=128 ((128/16)<<24)
#define IDESC 0x8200010u

// Feature gate: tcgen05/TMA inline PTX only exists in arch-'a' compilation passes.
#if defined(__CUDA_ARCH__) && (defined(__CUDA_ARCH_FEAT_SM103_ALL) || defined(__CUDA_ARCH_FEAT_SM100_ALL) || defined(__CUDA_ARCH_FEAT_SM101_ALL))
#define HAS_TCGEN05 1
#else
#define HAS_TCGEN05 0
#endif

// --------------------------- persistent scratch ---------------------------
__device__ __align__(1024) __half g_W1d[(size_t)HH * (2*DD)];  // [4096][2048] hi|lo
__device__ __align__(1024) __half g_W2d[(size_t)DD * (2*HH)];  // [1024][8192] hi|lo
__device__ __align__(1024) __half g_xe [(size_t)BB * DD];      // eval input fp16
__device__ __align__(1024) __half g_h  [(size_t)BB * HH];      // tanh activations fp16
__device__ __align__(1024) float  g_k  [(size_t)BB * DD];      // current RHS k
__device__ __align__(1024) float  g_acc[(size_t)BB * DD];      // RK4 accumulator

#if HAS_TCGEN05
// ------------------------------ PTX helpers -------------------------------
__device__ __forceinline__ uint32_t smem_u32(const void* p) {
    uint32_t a;
    asm("{ .reg .u64 t; cvta.to.shared.u64 t, %1; cvt.u32.u64 %0, t; }" : "=r"(a) : "l"(p));
    return a;
}

__device__ __forceinline__ void mbar_init(uint32_t mbar, uint32_t count) {
    asm volatile("mbarrier.init.shared.b64 [%0], %1;" :: "r"(mbar), "r"(count) : "memory");
}
__device__ __forceinline__ void mbar_expect_tx(uint32_t mbar, uint32_t bytes) {
    asm volatile("mbarrier.arrive.expect_tx.shared.b64 _, [%0], %1;" :: "r"(mbar), "r"(bytes) : "memory");
}
// Bounded wait: polls up to ~4M times (~0.3 s) then gives up. In a correctly
// functioning pipeline the first poll nearly always succeeds; the bound only
// converts a would-be hang (600 s container kill) into a finishing run whose
// rel_err/timing tells us which barrier starved.
__device__ __forceinline__ void mbar_wait(uint32_t mbar, uint32_t parity) {
    for (int i = 0; i < 4000000; i++) {
        uint32_t done;
        asm volatile(
            "{\n\t.reg .pred P;\n\t"
            "mbarrier.try_wait.parity.acquire.cta.shared::cta.b64 P, [%1], %2;\n\t"
            "selp.b32 %0, 1, 0, P;\n\t}"
            : "=r"(done) : "r"(mbar), "r"(parity) : "memory");
        if (done) return;
    }
}

__device__ __forceinline__ void tma_load_2d(uint32_t smem_dst, const CUtensorMap* map,
                                            int32_t cx, int32_t cy, uint32_t mbar) {
    asm volatile(
        "cp.async.bulk.tensor.2d.shared::cta.global.tile.mbarrier::complete_tx::bytes "
        "[%0], [%1, {%2, %3}], [%4];"
        :: "r"(smem_dst), "l"(map), "r"(cx), "r"(cy), "r"(mbar) : "memory");
}

// SW128 K-major smem descriptor (layout=2, version=1, SBO=64, LBO=1)
__device__ __forceinline__ uint64_t make_desc(uint32_t addr) {
    const uint64_t base = (uint64_t(2) << 61) | (uint64_t(1) << 46) |
                          (uint64_t(64) << 32) | (uint64_t(1) << 16);
    return base | ((uint64_t)(addr >> 4) & 0x3FFF);
}

__device__ __forceinline__ void mma_f16_ss(uint32_t d_tmem, uint64_t a_desc, uint64_t b_desc,
                                           uint32_t idesc, uint32_t enable) {
    asm volatile(
        "{\n\t.reg .pred p;\n\t"
        "setp.ne.u32 p, %5, 0;\n\t"
        "tcgen05.mma.cta_group::1.kind::f16 [%0], %1, %2, %3, {%4, %4, %4, %4}, p;\n\t}"
        :: "r"(d_tmem), "l"(a_desc), "l"(b_desc), "r"(idesc), "r"(0u), "r"(enable) : "memory");
}
__device__ __forceinline__ void tc_commit(uint32_t mbar) {
    asm volatile(
        "tcgen05.commit.cta_group::1.mbarrier::arrive::one.shared::cluster.b64 [%0];"
        :: "r"(mbar) : "memory");
}

#define TC_ALLOC(slot, n)  asm volatile("tcgen05.alloc.cta_group::1.sync.aligned.shared::cta.b32 [%0], %1;" :: "r"(slot), "r"((uint32_t)(n)) : "memory")
#define TC_RELINQ()        asm volatile("tcgen05.relinquish_alloc_permit.cta_group::1.sync.aligned;")
#define TC_DEALLOC(t, n)   asm volatile("tcgen05.dealloc.cta_group::1.sync.aligned.b32 %0, %1;" :: "r"(t), "r"((uint32_t)(n)))
#define TC_WAIT_LD()       asm volatile("tcgen05.wait::ld.sync.aligned;" ::: "memory")
#define TC_FENCE_AFTER()   asm volatile("tcgen05.fence::after_thread_sync;" ::: "memory")

#define LDTM_X32(r, addr) \
    asm volatile( \
        "tcgen05.ld.sync.aligned.32x32b.x32.b32 " \
        "{%0, %1, %2, %3, %4, %5, %6, %7, " \
        " %8, %9, %10, %11, %12, %13, %14, %15, " \
        " %16, %17, %18, %19, %20, %21, %22, %23, " \
        " %24, %25, %26, %27, %28, %29, %30, %31}, [%32];" \
        : "=r"((r)[0]),  "=r"((r)[1]),  "=r"((r)[2]),  "=r"((r)[3]), \
          "=r"((r)[4]),  "=r"((r)[5]),  "=r"((r)[6]),  "=r"((r)[7]), \
          "=r"((r)[8]),  "=r"((r)[9]),  "=r"((r)[10]), "=r"((r)[11]), \
          "=r"((r)[12]), "=r"((r)[13]), "=r"((r)[14]), "=r"((r)[15]), \
          "=r"((r)[16]), "=r"((r)[17]), "=r"((r)[18]), "=r"((r)[19]), \
          "=r"((r)[20]), "=r"((r)[21]), "=r"((r)[22]), "=r"((r)[23]), \
          "=r"((r)[24]), "=r"((r)[25]), "=r"((r)[26]), "=r"((r)[27]), \
          "=r"((r)[28]), "=r"((r)[29]), "=r"((r)[30]), "=r"((r)[31]) \
        : "r"(addr))
#endif  // HAS_TCGEN05

// ------------------------------- GEMM kernel ------------------------------
// C[m,n] = A[m,:] . W[n,:]  (TN), fp32 accumulate.
// tcgen05 path: W is hi/lo fp16 split via tmB; fallback path: Wraw fp32.
// mode 0:               outH = fp16(tanh(C + bias))                 (GEMM1)
// mode 1, !last:        v = C + bias; outK = v;
//                       outAcc = first ? v : outAcc + wcoef*v       (GEMM2 e0..2)
// mode 1, last:         v = C + bias; xn = xcur + s6*(outAcc + v);
//                       xcur = xn; xeout = fp16(xn)                 (GEMM2 e3)
__global__ void __launch_bounds__(256, 1) gemm_kernel(
    const __grid_constant__ CUtensorMap tmA,
    const __grid_constant__ CUtensorMap tmB,
    int nchunks, int korig,
    const float* __restrict__ bias,
    int mode,
    __half* __restrict__ outH,
    float* __restrict__ outK,
    float* __restrict__ outAcc,
    float* __restrict__ xcur,
    __half* __restrict__ xeout,
    float wcoef, int first, int last, float s6, int nout,
    const __half* __restrict__ Araw,
    const float* __restrict__ Wraw)
{
#if HAS_TCGEN05
    extern __shared__ char smem[];
    uint32_t sbase = smem_u32(smem);
    uint32_t tile0 = (sbase + 1023u) & ~1023u;
    uint32_t ctrl  = tile0 + STAGES * CHUNK_BYTES;
    uint32_t mb_full  = ctrl;           // 4 barriers * 8B
    uint32_t mb_empty = ctrl + 32;      // 4 barriers * 8B
    uint32_t mb_done  = ctrl + 64;
    uint32_t tmem_slot = ctrl + 80;

    int tid = threadIdx.x, wid = tid >> 5, lane = tid & 31;
    int m0 = blockIdx.y * BM;
    int n0 = blockIdx.x * BN;

    if (wid == 0) { TC_ALLOC(tmem_slot, 256); }
    if (tid == 0) {
        for (int s = 0; s < STAGES; s++) {
            mbar_init(mb_full  + 8*s, 1);
            mbar_init(mb_empty + 8*s, 1);
        }
        mbar_init(mb_done, 1);
    }
    __syncthreads();

    uint32_t tmem;
    asm volatile("ld.shared.b32 %0, [%1];" : "=r"(tmem) : "r"(tmem_slot));

    // ---- producer: warp 4, single thread ----
    if (wid == 4 && lane == 0) {
        int s = 0; uint32_t ph = 1;
        for (int c = 0; c < nchunks; c++) {
            mbar_wait(mb_empty + 8*s, ph);
            uint32_t st = tile0 + s * CHUNK_BYTES;
            mbar_expect_tx(mb_full + 8*s, CHUNK_BYTES);
            tma_load_2d(st,                 &tmA, c*BK,         m0, mb_full + 8*s);
            tma_load_2d(st + TILE_BYTES,    &tmB, c*BK,         n0, mb_full + 8*s);
            tma_load_2d(st + 2*TILE_BYTES,  &tmB, korig + c*BK, n0, mb_full + 8*s);
            if (++s == STAGES) { s = 0; ph ^= 1; }
        }
    }

    // ---- MMA issuer: warp 0, single thread ----
    if (wid == 0 && lane == 0) {
        int s = 0; uint32_t ph = 0;
        uint32_t enh = 0, enl = 0;
        for (int c = 0; c < nchunks; c++) {
            mbar_wait(mb_full + 8*s, ph);
            uint32_t st = tile0 + s * CHUNK_BYTES;
            uint64_t da  = make_desc(st);
            uint64_t dbh = make_desc(st + TILE_BYTES);
            uint64_t dbl = make_desc(st + 2*TILE_BYTES);
            #pragma unroll
            for (int k = 0; k < 4; k++) {
                mma_f16_ss(tmem,       da + 2*k, dbh + 2*k, IDESC, enh); enh = 1;
                mma_f16_ss(tmem + 128, da + 2*k, dbl + 2*k, IDESC, enl); enl = 1;
            }
            tc_commit(mb_empty + 8*s);
            if (++s == STAGES) { s = 0; ph ^= 1; }
        }
        tc_commit(mb_done);
    }

    __syncthreads();
    mbar_wait(mb_done, 0);
    TC_FENCE_AFTER();

    // ---- epilogue: warps 0-3 (one TMEM subpartition each) ----
    if (wid < 4) {
        int m = m0 + wid * 32 + lane;
        for (int nb = 0; nb < 4; nb++) {
            uint32_t rh[32], rl[32];
            LDTM_X32(rh, tmem + nb * 32);
            LDTM_X32(rl, tmem + 128 + nb * 32);
            TC_WAIT_LD();
            int nc = n0 + nb * 32;
            if (mode == 0) {
                uint32_t packed[16];
                #pragma unroll
                for (int j = 0; j < 16; j++) {
                    float v0 = __uint_as_float(rh[2*j])   + LO_INV * __uint_as_float(rl[2*j])   + bias[nc + 2*j];
                    float v1 = __uint_as_float(rh[2*j+1]) + LO_INV * __uint_as_float(rl[2*j+1]) + bias[nc + 2*j+1];
                    __half2 h2 = __floats2half2_rn(tanhf(v0), tanhf(v1));
                    packed[j] = *reinterpret_cast<uint32_t*>(&h2);
                }
                uint4* dst = reinterpret_cast<uint4*>(outH + (size_t)m * nout + nc);
                #pragma unroll
                for (int q = 0; q < 4; q++) dst[q] = reinterpret_cast<uint4*>(packed)[q];
            } else {
                float vals[32];
                #pragma unroll
                for (int j = 0; j < 32; j++)
                    vals[j] = __uint_as_float(rh[j]) + LO_INV * __uint_as_float(rl[j]) + bias[nc + j];
                size_t off = (size_t)m * nout + nc;
                if (!last) {
                    float4* dk = reinterpret_cast<float4*>(outK + off);
                    float4* da = reinterpret_cast<float4*>(outAcc + off);
                    #pragma unroll
                    for (int q = 0; q < 8; q++) {
                        float4 v = reinterpret_cast<float4*>(vals)[q];
                        dk[q] = v;
                        float4 a;
                        if (first) {
                            a = v;
                        } else {
                            a = da[q];
                            a.x += wcoef * v.x; a.y += wcoef * v.y;
                            a.z += wcoef * v.z; a.w += wcoef * v.w;
                        }
                        da[q] = a;
                    }
                } else {
                    // final eval of the RK4 step: x += s6*(acc + k4); emit fp16 state
                    const float4* da = reinterpret_cast<const float4*>(outAcc + off);
                    float4* dx = reinterpret_cast<float4*>(xcur + off);
                    uint32_t packed[16];
                    #pragma unroll
                    for (int q = 0; q < 8; q++) {
                        float4 v = reinterpret_cast<float4*>(vals)[q];
                        float4 a = da[q];
                        float4 xo = dx[q];
                        float4 xn;
                        xn.x = fmaf(s6, a.x + v.x, xo.x);
                        xn.y = fmaf(s6, a.y + v.y, xo.y);
                        xn.z = fmaf(s6, a.z + v.z, xo.z);
                        xn.w = fmaf(s6, a.w + v.w, xo.w);
                        dx[q] = xn;
                        __half2 h0 = __floats2half2_rn(xn.x, xn.y);
                        __half2 h1 = __floats2half2_rn(xn.z, xn.w);
                        packed[2*q]   = *reinterpret_cast<uint32_t*>(&h0);
                        packed[2*q+1] = *reinterpret_cast<uint32_t*>(&h1);
                    }
                    uint4* de = reinterpret_cast<uint4*>(xeout + off);
                    #pragma unroll
                    for (int q = 0; q < 4; q++) de[q] = reinterpret_cast<uint4*>(packed)[q];
                }
            }
        }
    }

    __syncthreads();
    if (wid == 0) { TC_RELINQ(); TC_DEALLOC(tmem, 256); }

#else  // ---------------- fallback: fp32 FFMA tiled GEMM (plain sm_103) ----
    extern __shared__ char smem[];
    float* As = reinterpret_cast<float*>(smem);          // [16][128] k-major
    float* Bs = reinterpret_cast<float*>(smem + 8192);   // [16][128]

    const int K = korig;
    const int tid = threadIdx.x;
    const int m0 = blockIdx.y * BM;
    const int n0 = blockIdx.x * BN;
    const int tx = tid & 15, ty = tid >> 4;              // 16x16 thread grid

    float acc[8][8];
    #pragma unroll
    for (int i = 0; i < 8; i++)
        #pragma unroll
        for (int j = 0; j < 8; j++) acc[i][j] = 0.0f;

    const int lr = tid >> 1;            // 0..127 (row within tile)
    const int lc = (tid & 1) * 8;       // 0 or 8 (k offset)

    for (int k0 = 0; k0 < K; k0 += 16) {
        {
            uint4 v = *reinterpret_cast<const uint4*>(Araw + (size_t)(m0 + lr) * K + k0 + lc);
            const __half* hp = reinterpret_cast<const __half*>(&v);
            #pragma unroll
            for (int j = 0; j < 8; j++) As[(lc + j) * 128 + lr] = __half2float(hp[j]);
        }
        {
            const float* src = Wraw + (size_t)(n0 + lr) * K + k0 + lc;
            float4 v1 = reinterpret_cast<const float4*>(src)[0];
            float4 v2 = reinterpret_cast<const float4*>(src)[1];
            Bs[(lc + 0) * 128 + lr] = v1.x; Bs[(lc + 1) * 128 + lr] = v1.y;
            Bs[(lc + 2) * 128 + lr] = v1.z; Bs[(lc + 3) * 128 + lr] = v1.w;
            Bs[(lc + 4) * 128 + lr] = v2.x; Bs[(lc + 5) * 128 + lr] = v2.y;
            Bs[(lc + 6) * 128 + lr] = v2.z; Bs[(lc + 7) * 128 + lr] = v2.w;
        }
        __syncthreads();
        #pragma unroll
        for (int kk = 0; kk < 16; kk++) {
            float a[8], b[8];
            #pragma unroll
            for (int i = 0; i < 8; i++) a[i] = As[kk * 128 + ty * 8 + i];
            #pragma unroll
            for (int j = 0; j < 8; j++) b[j] = Bs[kk * 128 + tx * 8 + j];
            #pragma unroll
            for (int i = 0; i < 8; i++)
                #pragma unroll
                for (int j = 0; j < 8; j++) acc[i][j] = fmaf(a[i], b[j], acc[i][j]);
        }
        __syncthreads();
    }

    #pragma unroll
    for (int i = 0; i < 8; i++) {
        int m = m0 + ty * 8 + i;
        #pragma unroll
        for (int j = 0; j < 8; j++) {
            int n = n0 + tx * 8 + j;
            float v = acc[i][j] + bias[n];
            if (mode == 0) {
                outH[(size_t)m * nout + n] = __float2half_rn(tanhf(v));
            } else {
                size_t o = (size_t)m * nout + n;
                if (!last) {
                    outK[o] = v;
                    outAcc[o] = first ? v : fmaf(wcoef, v, outAcc[o]);
                } else {
                    float xn = fmaf(s6, outAcc[o] + v, xcur[o]);
                    xcur[o] = xn;
                    xeout[o] = __float2half_rn(xn);
                }
            }
        }
    }
    (void)nchunks;
#endif
}

// --------------------------- elementwise kernels --------------------------
__global__ void wsplit_kernel(const float* __restrict__ W, __half* __restrict__ Wd,
                              int rows, int kk)
{
    int i = blockIdx.x * blockDim.x + threadIdx.x;
    if (i >= rows * kk) return;
    int r = i / kk, c = i - r * kk;
    float w = W[i];
    __half hi = __float2half_rn(w);
    __half lo = __float2half_rn((w - __half2float(hi)) * LO_SCALE);
    Wd[(size_t)r * (2*kk) + c]      = hi;
    Wd[(size_t)r * (2*kk) + kk + c] = lo;
}

__global__ void prep_kernel(const float* __restrict__ xc, const float* __restrict__ kv,
                            __half* __restrict__ xe, float cc, int n)
{
    int i = blockIdx.x * blockDim.x + threadIdx.x;
    if (i >= n) return;
    float v = xc[i];
    if (cc != 0.0f) v = fmaf(cc, kv[i], v);
    xe[i] = __float2half_rn(v);
}

// ------------------------------- host side --------------------------------
typedef CUresult (*EncodeTiledFn)(
    CUtensorMap*, CUtensorMapDataType, cuuint32_t, void*,
    const cuuint64_t*, const cuuint64_t*, const cuuint32_t*, const cuuint32_t*,
    CUtensorMapInterleave, CUtensorMapSwizzle, CUtensorMapL2promotion, CUtensorMapFloatOOBfill);

static void encode_2d_f16(EncodeTiledFn fn, CUtensorMap* m, void* ptr,
                          uint64_t d0, uint64_t d1)
{
    if (!fn) return;
    cuuint64_t dims[2]    = {d0, d1};
    cuuint64_t strides[1] = {d0 * 2};           // bytes per row
    cuuint32_t box[2]     = {BK, BM};           // 64 fp16 = 128 B, 128 rows
    cuuint32_t es[2]      = {1, 1};
    fn(m, CU_TENSOR_MAP_DATA_TYPE_FLOAT16, 2, ptr, dims, strides, box, es,
       CU_TENSOR_MAP_INTERLEAVE_NONE, CU_TENSOR_MAP_SWIZZLE_128B,
       CU_TENSOR_MAP_L2_PROMOTION_L2_128B, CU_TENSOR_MAP_FLOAT_OOB_FILL_NONE);
}

extern "C" void kernel_launch(void* const* d_in, const int* in_sizes, int n_in,
                              void* d_out, int out_size)
{
    const float* x  = (const float*)d_in[0];
    const float* W1 = (const float*)d_in[1];
    const float* b1 = (const float*)d_in[2];
    const float* W2 = (const float*)d_in[3];
    const float* b2 = (const float*)d_in[4];
    float* xc = (float*)d_out;                      // ODE state lives in d_out

    void *pW1d, *pW2d, *pxe, *ph, *pk, *pacc;
    cudaGetSymbolAddress(&pW1d, g_W1d);
    cudaGetSymbolAddress(&pW2d, g_W2d);
    cudaGetSymbolAddress(&pxe,  g_xe);
    cudaGetSymbolAddress(&ph,   g_h);
    cudaGetSymbolAddress(&pk,   g_k);
    cudaGetSymbolAddress(&pacc, g_acc);

    EncodeTiledFn encode_fn = nullptr;
    cudaDriverEntryPointQueryResult qres;
    cudaGetDriverEntryPoint("cuTensorMapEncodeTiled", (void**)&encode_fn,
                            cudaEnableDefault, &qres);

    cudaFuncSetAttribute(gemm_kernel, cudaFuncAttributeMaxDynamicSharedMemorySize, SMEM_REQ);

    alignas(64) CUtensorMap tmA1, tmB1, tmA2, tmB2;
    memset(&tmA1, 0, sizeof(tmA1)); memset(&tmB1, 0, sizeof(tmB1));
    memset(&tmA2, 0, sizeof(tmA2)); memset(&tmB2, 0, sizeof(tmB2));
    encode_2d_f16(encode_fn, &tmA1, pxe,  DD,     BB);   // xe  [4096 x 1024]
    encode_2d_f16(encode_fn, &tmB1, pW1d, 2*DD,   HH);   // W1d [4096 x 2048]
    encode_2d_f16(encode_fn, &tmA2, ph,   HH,     BB);   // h   [4096 x 4096]
    encode_2d_f16(encode_fn, &tmB2, pW2d, 2*HH,   DD);   // W2d [1024 x 8192]

    const int nelem = BB * DD;
    const int EB = 256;
    const int EG = (nelem + EB - 1) / EB;

    // init state + fp16 state + weight split (deterministic per call)
    cudaMemcpyAsync(xc, x, (size_t)nelem * sizeof(float), cudaMemcpyDeviceToDevice);
    prep_kernel<<<EG, EB>>>(xc, (const float*)pk, (__half*)pxe, 0.0f, nelem);
    wsplit_kernel<<<(HH*DD + EB - 1)/EB, EB>>>(W1, (__half*)pW1d, HH, DD);
    wsplit_kernel<<<(DD*HH + EB - 1)/EB, EB>>>(W2, (__half*)pW2d, DD, HH);

    const float dt = 1.0f / (float)NSTEPS;
    const float s6 = dt / 6.0f;
    const float cs[4] = {0.0f, 0.5f*dt, 0.5f*dt, dt};
    const float ws[4] = {1.0f, 2.0f, 2.0f, 1.0f};

    for (int s = 0; s < NSTEPS; s++) {
        for (int e = 0; e < 4; e++) {
            if (e > 0)
                prep_kernel<<<EG, EB>>>(xc, (const float*)pk, (__half*)pxe, cs[e], nelem);
            // GEMM1: h = tanh(xe @ W1^T + b1)
            gemm_kernel<<<dim3(HH/BN, BB/BM), 256, SMEM_REQ>>>(
                tmA1, tmB1, DD/BK, DD, b1, 0,
                (__half*)ph, nullptr, nullptr, nullptr, nullptr,
                0.0f, 0, 0, 0.0f, HH,
                (const __half*)pxe, W1);
            // GEMM2: k = h @ W2^T + b2 ; RK4 accumulate / final state update
            gemm_kernel<<<dim3(DD/BN, BB/BM), 256, SMEM_REQ>>>(
                tmA2, tmB2, HH/BK, HH, b2, 1,
                nullptr, (float*)pk, (float*)pacc, xc, (__half*)pxe,
                ws[e], (e == 0) ? 1 : 0, (e == 3) ? 1 : 0, s6, DD,
                (const __half*)ph, W2);
        }
    }
    (void)in_sizes; (void)n_in; (void)out_size;
}

// round 8
// speedup vs baseline: 1.0480x; 1.0480x over previous
#include <cuda_runtime.h>
#include <cuda.h>
#include <cuda_fp16.h>
#include <cstdint>
#include <cstddef>
#include <cstring>

// ----------------------------- problem sizes ------------------------------
#define BB 4096   // batch
#define DD 1024   // input dim
#define HH 4096   // hidden dim
#define NSTEPS 64

// ------------------------------ GEMM tiling -------------------------------
// cta_group::2 pair tile: M=256 (128 rows per CTA), N=256 (128 B-rows per CTA)
#define BMP 256               // pair M
#define BNP 256               // pair N
#define BK 64                 // fp16 elements per K-chunk = 128 bytes (SW128 atom)
#define STAGES 4
#define TILE_BYTES 16384      // 128 rows * 128 B
#define CHUNK_BYTES (3*TILE_BYTES)   // per-CTA: A(16K) + Bhi_half(16K) + Blo_half(16K)
#define PAIR_CHUNK_BYTES (2*CHUNK_BYTES)  // expect_tx on leader = both CTAs
#define SMEM_REQ (STAGES*CHUNK_BYTES + 2048)

#define LO_SCALE 1024.0f
#define LO_INV   (1.0f/1024.0f)

// idesc kind::f16 cg2: dtype=F32(1<<4), atype/btype=F16(0), N=256 ((256/8)<<17), M=256 ((256/16)<<24)
#define IDESC_CG2 ((1u<<4) | (32u<<17) | (16u<<24))

// Feature gate: tcgen05/TMA inline PTX only exists in arch-'a' compilation passes.
#if defined(__CUDA_ARCH__) && (defined(__CUDA_ARCH_FEAT_SM103_ALL) || defined(__CUDA_ARCH_FEAT_SM100_ALL) || defined(__CUDA_ARCH_FEAT_SM101_ALL))
#define HAS_TCGEN05 1
#else
#define HAS_TCGEN05 0
#endif

// --------------------------- persistent scratch ---------------------------
__device__ __align__(1024) __half g_W1d[(size_t)HH * (2*DD)];  // [4096][2048] hi|lo
__device__ __align__(1024) __half g_W2d[(size_t)DD * (2*HH)];  // [1024][8192] hi|lo
__device__ __align__(1024) __half g_xe [(size_t)BB * DD];      // eval input fp16
__device__ __align__(1024) __half g_h  [(size_t)BB * HH];      // tanh activations fp16
__device__ __align__(1024) float  g_k  [(size_t)BB * DD];      // current RHS k
__device__ __align__(1024) float  g_acc[(size_t)BB * DD];      // RK4 accumulator

__device__ __forceinline__ float tanh_fast(float x) {
    float y; asm("tanh.approx.f32 %0, %1;" : "=f"(y) : "f"(x)); return y;
}

#if HAS_TCGEN05
// ------------------------------ PTX helpers -------------------------------
__device__ __forceinline__ uint32_t smem_u32(const void* p) {
    uint32_t a;
    asm("{ .reg .u64 t; cvta.to.shared.u64 t, %1; cvt.u32.u64 %0, t; }" : "=r"(a) : "l"(p));
    return a;
}
__device__ __forceinline__ uint32_t ctarank() {
    uint32_t r; asm("mov.u32 %0, %%cluster_ctarank;" : "=r"(r)); return r;
}
__device__ __forceinline__ void cluster_sync() {
    asm volatile("barrier.cluster.arrive.aligned;" ::: "memory");
    asm volatile("barrier.cluster.wait.aligned;" ::: "memory");
}

__device__ __forceinline__ void mbar_init(uint32_t mbar, uint32_t count) {
    asm volatile("mbarrier.init.shared.b64 [%0], %1;" :: "r"(mbar), "r"(count) : "memory");
}
__device__ __forceinline__ void mbar_expect_tx(uint32_t mbar, uint32_t bytes) {
    asm volatile("mbarrier.arrive.expect_tx.shared.b64 _, [%0], %1;" :: "r"(mbar), "r"(bytes) : "memory");
}
// Bounded wait: converts a would-be hang into a finishing (diagnosable) run.
__device__ __forceinline__ void mbar_wait(uint32_t mbar, uint32_t parity) {
    for (int i = 0; i < 4000000; i++) {
        uint32_t done;
        asm volatile(
            "{\n\t.reg .pred P;\n\t"
            "mbarrier.try_wait.parity.acquire.cta.shared::cta.b64 P, [%1], %2;\n\t"
            "selp.b32 %0, 1, 0, P;\n\t}"
            : "=r"(done) : "r"(mbar), "r"(parity) : "memory");
        if (done) return;
    }
}

// cg2 TMA: data lands in this CTA's SMEM; complete_tx targets the LEADER CTA's
// barrier (bit 24 of the cluster-mapped barrier address cleared).
__device__ __forceinline__ void tma_load_2d_cg2(uint32_t smem_dst, const CUtensorMap* map,
                                                int32_t cx, int32_t cy, uint32_t mbar) {
    uint32_t lb = mbar & 0xFEFFFFFFu;
    asm volatile(
        "cp.async.bulk.tensor.2d.cta_group::2.shared::cluster.global.tile.mbarrier::complete_tx::bytes "
        "[%0], [%1, {%2, %3}], [%4];"
        :: "r"(smem_dst), "l"(map), "r"(cx), "r"(cy), "r"(lb) : "memory");
}

// SW128 K-major smem descriptor (layout=2, version=1, SBO=64, LBO=1)
__device__ __forceinline__ uint64_t make_desc(uint32_t addr) {
    const uint64_t base = (uint64_t(2) << 61) | (uint64_t(1) << 46) |
                          (uint64_t(64) << 32) | (uint64_t(1) << 16);
    return base | ((uint64_t)(addr >> 4) & 0x3FFF);
}

__device__ __forceinline__ void mma_f16_ss_cg2(uint32_t d_tmem, uint64_t a_desc, uint64_t b_desc,
                                               uint32_t idesc, uint32_t enable) {
    asm volatile(
        "{\n\t.reg .pred p;\n\t"
        "setp.ne.u32 p, %5, 0;\n\t"
        "tcgen05.mma.cta_group::2.kind::f16 [%0], %1, %2, %3, "
        "{%4, %4, %4, %4, %4, %4, %4, %4}, p;\n\t}"
        :: "r"(d_tmem), "l"(a_desc), "l"(b_desc), "r"(idesc), "r"(0u), "r"(enable) : "memory");
}
__device__ __forceinline__ void tc_commit_mc2(uint32_t mbar) {
    asm volatile(
        "tcgen05.commit.cta_group::2.mbarrier::arrive::one.shared::cluster.multicast::cluster.b64 [%0], %1;"
        :: "r"(mbar), "h"((uint16_t)0x3) : "memory");
}

#define TC_ALLOC_CG2(slot, n)  asm volatile("tcgen05.alloc.cta_group::2.sync.aligned.shared::cta.b32 [%0], %1;" :: "r"(slot), "r"((uint32_t)(n)) : "memory")
#define TC_RELINQ_CG2()        asm volatile("tcgen05.relinquish_alloc_permit.cta_group::2.sync.aligned;")
#define TC_DEALLOC_CG2(t, n)   asm volatile("tcgen05.dealloc.cta_group::2.sync.aligned.b32 %0, %1;" :: "r"(t), "r"((uint32_t)(n)))
#define TC_WAIT_LD()       asm volatile("tcgen05.wait::ld.sync.aligned;" ::: "memory")
#define TC_FENCE_AFTER()   asm volatile("tcgen05.fence::after_thread_sync;" ::: "memory")

#define LDTM_X32(r, addr) \
    asm volatile( \
        "tcgen05.ld.sync.aligned.32x32b.x32.b32 " \
        "{%0, %1, %2, %3, %4, %5, %6, %7, " \
        " %8, %9, %10, %11, %12, %13, %14, %15, " \
        " %16, %17, %18, %19, %20, %21, %22, %23, " \
        " %24, %25, %26, %27, %28, %29, %30, %31}, [%32];" \
        : "=r"((r)[0]),  "=r"((r)[1]),  "=r"((r)[2]),  "=r"((r)[3]), \
          "=r"((r)[4]),  "=r"((r)[5]),  "=r"((r)[6]),  "=r"((r)[7]), \
          "=r"((r)[8]),  "=r"((r)[9]),  "=r"((r)[10]), "=r"((r)[11]), \
          "=r"((r)[12]), "=r"((r)[13]), "=r"((r)[14]), "=r"((r)[15]), \
          "=r"((r)[16]), "=r"((r)[17]), "=r"((r)[18]), "=r"((r)[19]), \
          "=r"((r)[20]), "=r"((r)[21]), "=r"((r)[22]), "=r"((r)[23]), \
          "=r"((r)[24]), "=r"((r)[25]), "=r"((r)[26]), "=r"((r)[27]), \
          "=r"((r)[28]), "=r"((r)[29]), "=r"((r)[30]), "=r"((r)[31]) \
        : "r"(addr))
#endif  // HAS_TCGEN05

// ------------------------------- GEMM kernel ------------------------------
// Pair (cluster of 2) computes C[256, 256] = A[256,K] . W[256,K]^T, fp32 acc.
// W = W_hi + W_lo/1024 (fp16 split). Per-CTA: own 128 A-rows, own 128 B-rows.
// mode 0:        outH = fp16(tanh(C + bias))                         (GEMM1)
// mode 1,!last:  v = C + bias; outK = v; outAcc = first? v : outAcc + wcoef*v
// mode 1, last:  v = C + bias; xn = xcur + s6*(outAcc + v); xcur=xn; xeout=fp16(xn)
__global__ void __launch_bounds__(256, 1) __cluster_dims__(2, 1, 1) gemm_kernel(
    const __grid_constant__ CUtensorMap tmA,
    const __grid_constant__ CUtensorMap tmB,
    int nchunks, int korig,
    const float* __restrict__ bias,
    int mode,
    __half* __restrict__ outH,
    float* __restrict__ outK,
    float* __restrict__ outAcc,
    float* __restrict__ xcur,
    __half* __restrict__ xeout,
    float wcoef, int first, int last, float s6, int nout,
    const __half* __restrict__ Araw,
    const float* __restrict__ Wraw)
{
#if HAS_TCGEN05
    extern __shared__ char smem[];
    uint32_t sbase = smem_u32(smem);
    uint32_t tile0 = (sbase + 1023u) & ~1023u;
    uint32_t ctrl  = tile0 + STAGES * CHUNK_BYTES;
    uint32_t mb_full  = ctrl;           // STAGES barriers * 8B (used on leader)
    uint32_t mb_empty = ctrl + 32;      // STAGES barriers * 8B (both CTAs)
    uint32_t mb_done  = ctrl + 64;
    uint32_t tmem_slot = ctrl + 80;

    int tid = threadIdx.x, wid = tid >> 5, lane = tid & 31;
    uint32_t rank = ctarank();
    int mself = blockIdx.y * BMP + (int)rank * 128;   // this CTA's A rows
    int n0    = (blockIdx.x >> 1) * BNP;              // pair N origin
    int nself = n0 + (int)rank * 128;                 // this CTA's B rows

    if (wid == 0) { TC_ALLOC_CG2(tmem_slot, 512); }
    if (tid == 0) {
        for (int s = 0; s < STAGES; s++) {
            mbar_init(mb_full  + 8*s, 1);
            mbar_init(mb_empty + 8*s, 1);
        }
        mbar_init(mb_done, 1);
    }
    __syncthreads();
    // peer barriers must be initialized before any cg2 TMA / multicast commit
    cluster_sync();

    uint32_t tmem;
    asm volatile("ld.shared.b32 %0, [%1];" : "=r"(tmem) : "r"(tmem_slot));

    // ---- producer: warp 4, single thread, BOTH CTAs ----
    if (wid == 4 && lane == 0) {
        int s = 0; uint32_t ph = 1;
        for (int c = 0; c < nchunks; c++) {
            mbar_wait(mb_empty + 8*s, ph);
            uint32_t st = tile0 + s * CHUNK_BYTES;
            if (rank == 0) mbar_expect_tx(mb_full + 8*s, PAIR_CHUNK_BYTES);
            tma_load_2d_cg2(st,                &tmA, c*BK,         mself, mb_full + 8*s);
            tma_load_2d_cg2(st + TILE_BYTES,   &tmB, c*BK,         nself, mb_full + 8*s);
            tma_load_2d_cg2(st + 2*TILE_BYTES, &tmB, korig + c*BK, nself, mb_full + 8*s);
            if (++s == STAGES) { s = 0; ph ^= 1; }
        }
    }

    // ---- MMA issuer: warp 0, single thread, LEADER only ----
    if (rank == 0 && wid == 0 && lane == 0) {
        int s = 0; uint32_t ph = 0;
        uint32_t enh = 0, enl = 0;
        for (int c = 0; c < nchunks; c++) {
            mbar_wait(mb_full + 8*s, ph);
            uint32_t st = tile0 + s * CHUNK_BYTES;
            uint64_t da  = make_desc(st);
            uint64_t dbh = make_desc(st + TILE_BYTES);
            uint64_t dbl = make_desc(st + 2*TILE_BYTES);
            #pragma unroll
            for (int k = 0; k < 4; k++) {
                mma_f16_ss_cg2(tmem,       da + 2*k, dbh + 2*k, IDESC_CG2, enh); enh = 1;
                mma_f16_ss_cg2(tmem + 256, da + 2*k, dbl + 2*k, IDESC_CG2, enl); enl = 1;
            }
            tc_commit_mc2(mb_empty + 8*s);     // arrives in BOTH CTAs' empty[s]
            if (++s == STAGES) { s = 0; ph ^= 1; }
        }
        tc_commit_mc2(mb_done);                 // arrives in BOTH CTAs' done
    }

    __syncthreads();
    mbar_wait(mb_done, 0);
    TC_FENCE_AFTER();

    // ---- epilogue: warps 0-3 (this CTA's 128 rows x 256 cols) ----
    if (wid < 4) {
        int m = mself + wid * 32 + lane;
        for (int nb = 0; nb < 8; nb++) {
            uint32_t rh[32], rl[32];
            LDTM_X32(rh, tmem + nb * 32);
            LDTM_X32(rl, tmem + 256 + nb * 32);
            TC_WAIT_LD();
            int nc = n0 + nb * 32;
            if (mode == 0) {
                uint32_t packed[16];
                #pragma unroll
                for (int j = 0; j < 16; j++) {
                    float v0 = __uint_as_float(rh[2*j])   + LO_INV * __uint_as_float(rl[2*j])   + bias[nc + 2*j];
                    float v1 = __uint_as_float(rh[2*j+1]) + LO_INV * __uint_as_float(rl[2*j+1]) + bias[nc + 2*j+1];
                    __half2 h2 = __floats2half2_rn(tanh_fast(v0), tanh_fast(v1));
                    packed[j] = *reinterpret_cast<uint32_t*>(&h2);
                }
                uint4* dst = reinterpret_cast<uint4*>(outH + (size_t)m * nout + nc);
                #pragma unroll
                for (int q = 0; q < 4; q++) dst[q] = reinterpret_cast<uint4*>(packed)[q];
            } else {
                float vals[32];
                #pragma unroll
                for (int j = 0; j < 32; j++)
                    vals[j] = __uint_as_float(rh[j]) + LO_INV * __uint_as_float(rl[j]) + bias[nc + j];
                size_t off = (size_t)m * nout + nc;
                if (!last) {
                    float4* dk = reinterpret_cast<float4*>(outK + off);
                    float4* da = reinterpret_cast<float4*>(outAcc + off);
                    #pragma unroll
                    for (int q = 0; q < 8; q++) {
                        float4 v = reinterpret_cast<float4*>(vals)[q];
                        dk[q] = v;
                        float4 a;
                        if (first) {
                            a = v;
                        } else {
                            a = da[q];
                            a.x += wcoef * v.x; a.y += wcoef * v.y;
                            a.z += wcoef * v.z; a.w += wcoef * v.w;
                        }
                        da[q] = a;
                    }
                } else {
                    // final eval of the RK4 step: x += s6*(acc + k4); emit fp16 state
                    const float4* da = reinterpret_cast<const float4*>(outAcc + off);
                    float4* dx = reinterpret_cast<float4*>(xcur + off);
                    uint32_t packed[16];
                    #pragma unroll
                    for (int q = 0; q < 8; q++) {
                        float4 v = reinterpret_cast<float4*>(vals)[q];
                        float4 a = da[q];
                        float4 xo = dx[q];
                        float4 xn;
                        xn.x = fmaf(s6, a.x + v.x, xo.x);
                        xn.y = fmaf(s6, a.y + v.y, xo.y);
                        xn.z = fmaf(s6, a.z + v.z, xo.z);
                        xn.w = fmaf(s6, a.w + v.w, xo.w);
                        dx[q] = xn;
                        __half2 h0 = __floats2half2_rn(xn.x, xn.y);
                        __half2 h1 = __floats2half2_rn(xn.z, xn.w);
                        packed[2*q]   = *reinterpret_cast<uint32_t*>(&h0);
                        packed[2*q+1] = *reinterpret_cast<uint32_t*>(&h1);
                    }
                    uint4* de = reinterpret_cast<uint4*>(xeout + off);
                    #pragma unroll
                    for (int q = 0; q < 4; q++) de[q] = reinterpret_cast<uint4*>(packed)[q];
                }
            }
        }
    }

    __syncthreads();
    if (wid == 0) { TC_RELINQ_CG2(); TC_DEALLOC_CG2(tmem, 512); }
    // no CTA may exit while its SMEM might still be read by the peer's MMA path
    cluster_sync();

#else  // ---------------- fallback: fp32 FFMA tiled GEMM (plain sm_103) ----
    extern __shared__ char smem[];
    float* As = reinterpret_cast<float*>(smem);          // [16][128] k-major
    float* Bs = reinterpret_cast<float*>(smem + 8192);   // [16][128]

    const int K = korig;
    const int tid = threadIdx.x;
    const int m0 = blockIdx.y * BMP + (blockIdx.x & 1) * 128;
    const int pn0 = (blockIdx.x >> 1) * BNP;
    const int tx = tid & 15, ty = tid >> 4;              // 16x16 thread grid
    const int lr = tid >> 1;            // 0..127 (row within tile)
    const int lc = (tid & 1) * 8;       // 0 or 8 (k offset)

    for (int half = 0; half < 2; half++) {
        const int n0 = pn0 + half * 128;
        float acc[8][8];
        #pragma unroll
        for (int i = 0; i < 8; i++)
            #pragma unroll
            for (int j = 0; j < 8; j++) acc[i][j] = 0.0f;

        for (int k0 = 0; k0 < K; k0 += 16) {
            {
                uint4 v = *reinterpret_cast<const uint4*>(Araw + (size_t)(m0 + lr) * K + k0 + lc);
                const __half* hp = reinterpret_cast<const __half*>(&v);
                #pragma unroll
                for (int j = 0; j < 8; j++) As[(lc + j) * 128 + lr] = __half2float(hp[j]);
            }
            {
                const float* src = Wraw + (size_t)(n0 + lr) * K + k0 + lc;
                float4 v1 = reinterpret_cast<const float4*>(src)[0];
                float4 v2 = reinterpret_cast<const float4*>(src)[1];
                Bs[(lc + 0) * 128 + lr] = v1.x; Bs[(lc + 1) * 128 + lr] = v1.y;
                Bs[(lc + 2) * 128 + lr] = v1.z; Bs[(lc + 3) * 128 + lr] = v1.w;
                Bs[(lc + 4) * 128 + lr] = v2.x; Bs[(lc + 5) * 128 + lr] = v2.y;
                Bs[(lc + 6) * 128 + lr] = v2.z; Bs[(lc + 7) * 128 + lr] = v2.w;
            }
            __syncthreads();
            #pragma unroll
            for (int kk = 0; kk < 16; kk++) {
                float a[8], b[8];
                #pragma unroll
                for (int i = 0; i < 8; i++) a[i] = As[kk * 128 + ty * 8 + i];
                #pragma unroll
                for (int j = 0; j < 8; j++) b[j] = Bs[kk * 128 + tx * 8 + j];
                #pragma unroll
                for (int i = 0; i < 8; i++)
                    #pragma unroll
                    for (int j = 0; j < 8; j++) acc[i][j] = fmaf(a[i], b[j], acc[i][j]);
            }
            __syncthreads();
        }

        #pragma unroll
        for (int i = 0; i < 8; i++) {
            int m = m0 + ty * 8 + i;
            #pragma unroll
            for (int j = 0; j < 8; j++) {
                int n = n0 + tx * 8 + j;
                float v = acc[i][j] + bias[n];
                if (mode == 0) {
                    outH[(size_t)m * nout + n] = __float2half_rn(tanh_fast(v));
                } else {
                    size_t o = (size_t)m * nout + n;
                    if (!last) {
                        outK[o] = v;
                        outAcc[o] = first ? v : fmaf(wcoef, v, outAcc[o]);
                    } else {
                        float xn = fmaf(s6, outAcc[o] + v, xcur[o]);
                        xcur[o] = xn;
                        xeout[o] = __float2half_rn(xn);
                    }
                }
            }
        }
        __syncthreads();
    }
    (void)nchunks;
#endif
}

// --------------------------- elementwise kernels --------------------------
__global__ void wsplit_kernel(const float* __restrict__ W, __half* __restrict__ Wd,
                              int rows, int kk)
{
    int i = blockIdx.x * blockDim.x + threadIdx.x;
    if (i >= rows * kk) return;
    int r = i / kk, c = i - r * kk;
    float w = W[i];
    __half hi = __float2half_rn(w);
    __half lo = __float2half_rn((w - __half2float(hi)) * LO_SCALE);
    Wd[(size_t)r * (2*kk) + c]      = hi;
    Wd[(size_t)r * (2*kk) + kk + c] = lo;
}

__global__ void prep_kernel(const float* __restrict__ xc, const float* __restrict__ kv,
                            __half* __restrict__ xe, float cc, int n)
{
    int i = blockIdx.x * blockDim.x + threadIdx.x;
    if (i >= n) return;
    float v = xc[i];
    if (cc != 0.0f) v = fmaf(cc, kv[i], v);
    xe[i] = __float2half_rn(v);
}

// ------------------------------- host side --------------------------------
typedef CUresult (*EncodeTiledFn)(
    CUtensorMap*, CUtensorMapDataType, cuuint32_t, void*,
    const cuuint64_t*, const cuuint64_t*, const cuuint32_t*, const cuuint32_t*,
    CUtensorMapInterleave, CUtensorMapSwizzle, CUtensorMapL2promotion, CUtensorMapFloatOOBfill);

static void encode_2d_f16(EncodeTiledFn fn, CUtensorMap* m, void* ptr,
                          uint64_t d0, uint64_t d1)
{
    if (!fn) return;
    cuuint64_t dims[2]    = {d0, d1};
    cuuint64_t strides[1] = {d0 * 2};           // bytes per row
    cuuint32_t box[2]     = {BK, 128};          // 64 fp16 = 128 B, 128 rows
    cuuint32_t es[2]      = {1, 1};
    fn(m, CU_TENSOR_MAP_DATA_TYPE_FLOAT16, 2, ptr, dims, strides, box, es,
       CU_TENSOR_MAP_INTERLEAVE_NONE, CU_TENSOR_MAP_SWIZZLE_128B,
       CU_TENSOR_MAP_L2_PROMOTION_L2_128B, CU_TENSOR_MAP_FLOAT_OOB_FILL_NONE);
}

extern "C" void kernel_launch(void* const* d_in, const int* in_sizes, int n_in,
                              void* d_out, int out_size)
{
    const float* x  = (const float*)d_in[0];
    const float* W1 = (const float*)d_in[1];
    const float* b1 = (const float*)d_in[2];
    const float* W2 = (const float*)d_in[3];
    const float* b2 = (const float*)d_in[4];
    float* xc = (float*)d_out;                      // ODE state lives in d_out

    void *pW1d, *pW2d, *pxe, *ph, *pk, *pacc;
    cudaGetSymbolAddress(&pW1d, g_W1d);
    cudaGetSymbolAddress(&pW2d, g_W2d);
    cudaGetSymbolAddress(&pxe,  g_xe);
    cudaGetSymbolAddress(&ph,   g_h);
    cudaGetSymbolAddress(&pk,   g_k);
    cudaGetSymbolAddress(&pacc, g_acc);

    EncodeTiledFn encode_fn = nullptr;
    cudaDriverEntryPointQueryResult qres;
    cudaGetDriverEntryPoint("cuTensorMapEncodeTiled", (void**)&encode_fn,
                            cudaEnableDefault, &qres);

    cudaFuncSetAttribute(gemm_kernel, cudaFuncAttributeMaxDynamicSharedMemorySize, SMEM_REQ);

    alignas(64) CUtensorMap tmA1, tmB1, tmA2, tmB2;
    memset(&tmA1, 0, sizeof(tmA1)); memset(&tmB1, 0, sizeof(tmB1));
    memset(&tmA2, 0, sizeof(tmA2)); memset(&tmB2, 0, sizeof(tmB2));
    encode_2d_f16(encode_fn, &tmA1, pxe,  DD,     BB);   // xe  [4096 x 1024]
    encode_2d_f16(encode_fn, &tmB1, pW1d, 2*DD,   HH);   // W1d [4096 x 2048]
    encode_2d_f16(encode_fn, &tmA2, ph,   HH,     BB);   // h   [4096 x 4096]
    encode_2d_f16(encode_fn, &tmB2, pW2d, 2*HH,   DD);   // W2d [1024 x 8192]

    const int nelem = BB * DD;
    const int EB = 256;
    const int EG = (nelem + EB - 1) / EB;

    // init state + fp16 state + weight split (deterministic per call)
    cudaMemcpyAsync(xc, x, (size_t)nelem * sizeof(float), cudaMemcpyDeviceToDevice);
    prep_kernel<<<EG, EB>>>(xc, (const float*)pk, (__half*)pxe, 0.0f, nelem);
    wsplit_kernel<<<(HH*DD + EB - 1)/EB, EB>>>(W1, (__half*)pW1d, HH, DD);
    wsplit_kernel<<<(DD*HH + EB - 1)/EB, EB>>>(W2, (__half*)pW2d, DD, HH);

    const float dt = 1.0f / (float)NSTEPS;
    const float s6 = dt / 6.0f;
    const float cs[4] = {0.0f, 0.5f*dt, 0.5f*dt, dt};
    const float ws[4] = {1.0f, 2.0f, 2.0f, 1.0f};

    for (int s = 0; s < NSTEPS; s++) {
        for (int e = 0; e < 4; e++) {
            if (e > 0)
                prep_kernel<<<EG, EB>>>(xc, (const float*)pk, (__half*)pxe, cs[e], nelem);
            // GEMM1: h = tanh(xe @ W1^T + b1)  — pairs of CTAs (cluster 2)
            gemm_kernel<<<dim3(2*(HH/BNP), BB/BMP), 256, SMEM_REQ>>>(
                tmA1, tmB1, DD/BK, DD, b1, 0,
                (__half*)ph, nullptr, nullptr, nullptr, nullptr,
                0.0f, 0, 0, 0.0f, HH,
                (const __half*)pxe, W1);
            // GEMM2: k = h @ W2^T + b2 ; RK4 accumulate / final state update
            gemm_kernel<<<dim3(2*(DD/BNP), BB/BMP), 256, SMEM_REQ>>>(
                tmA2, tmB2, HH/BK, HH, b2, 1,
                nullptr, (float*)pk, (float*)pacc, xc, (__half*)pxe,
                ws[e], (e == 0) ? 1 : 0, (e == 3) ? 1 : 0, s6, DD,
                (const __half*)ph, W2);
        }
    }
    (void)in_sizes; (void)n_in; (void)out_size;
}

// round 9
// speedup vs baseline: 1.4082x; 1.3437x over previous
#include <cuda_runtime.h>
#include <cuda.h>
#include <cuda_fp16.h>
#include <cstdint>
#include <cstddef>
#include <cstring>

// ----------------------------- problem sizes ------------------------------
#define BB 4096   // batch
#define DD 1024   // input dim
#define HH 4096   // hidden dim
#define NSTEPS 64

// ------------------------------ GEMM tiling -------------------------------
// cta_group::2 pair tile: M=256 (128 rows/CTA), N=256 (128 B-rows/CTA)
#define BMP 256
#define BNP 256
#define BK 64                 // fp16 elements per K-chunk = 128 B (SW128 atom)
#define STAGES 6
#define TILE_BYTES 16384      // 128 rows * 128 B
#define CHUNK_BYTES (2*TILE_BYTES)        // per-CTA: A(16K) + B(16K)
#define PAIR_CHUNK_BYTES (2*CHUNK_BYTES)  // leader expect_tx covers both CTAs
#define SMEM_REQ (STAGES*CHUNK_BYTES + 2048)
#define NPAIRS 64             // persistent pairs (128 CTAs)
#define MT 16                 // M pair-tiles (BB/BMP) for both GEMMs

// idesc kind::f16 cg2: dtype=F32(1<<4), a/btype=F16, N=256, M=256
#define IDESC_CG2 ((1u<<4) | (32u<<17) | (16u<<24))

#if defined(__CUDA_ARCH__) && (defined(__CUDA_ARCH_FEAT_SM103_ALL) || defined(__CUDA_ARCH_FEAT_SM100_ALL) || defined(__CUDA_ARCH_FEAT_SM101_ALL))
#define HAS_TCGEN05 1
#else
#define HAS_TCGEN05 0
#endif

// --------------------------- persistent scratch ---------------------------
__device__ __align__(1024) __half g_W1h[(size_t)HH * DD];   // fp16 W1
__device__ __align__(1024) __half g_W2h[(size_t)DD * HH];   // fp16 W2
__device__ __align__(1024) __half g_xe [(size_t)BB * DD];   // eval input fp16
__device__ __align__(1024) __half g_h  [(size_t)BB * HH];   // tanh activations fp16
__device__ __align__(1024) float  g_acc[(size_t)BB * DD];   // RK4 accumulator

__device__ __forceinline__ float tanh_fast(float x) {
    float y; asm("tanh.approx.f32 %0, %1;" : "=f"(y) : "f"(x)); return y;
}

#if HAS_TCGEN05
// ------------------------------ PTX helpers -------------------------------
__device__ __forceinline__ uint32_t smem_u32(const void* p) {
    uint32_t a;
    asm("{ .reg .u64 t; cvta.to.shared.u64 t, %1; cvt.u32.u64 %0, t; }" : "=r"(a) : "l"(p));
    return a;
}
__device__ __forceinline__ uint32_t ctarank() {
    uint32_t r; asm("mov.u32 %0, %%cluster_ctarank;" : "=r"(r)); return r;
}
__device__ __forceinline__ void cluster_sync() {
    asm volatile("barrier.cluster.arrive.aligned;" ::: "memory");
    asm volatile("barrier.cluster.wait.aligned;" ::: "memory");
}
__device__ __forceinline__ void mbar_init(uint32_t mbar, uint32_t count) {
    asm volatile("mbarrier.init.shared.b64 [%0], %1;" :: "r"(mbar), "r"(count) : "memory");
}
__device__ __forceinline__ void mbar_expect_tx(uint32_t mbar, uint32_t bytes) {
    asm volatile("mbarrier.arrive.expect_tx.shared.b64 _, [%0], %1;" :: "r"(mbar), "r"(bytes) : "memory");
}
// Bounded wait: converts a would-be hang into a finishing (diagnosable) run.
__device__ __forceinline__ void mbar_wait(uint32_t mbar, uint32_t parity) {
    for (int i = 0; i < 4000000; i++) {
        uint32_t done;
        asm volatile(
            "{\n\t.reg .pred P;\n\t"
            "mbarrier.try_wait.parity.acquire.cta.shared::cta.b64 P, [%1], %2;\n\t"
            "selp.b32 %0, 1, 0, P;\n\t}"
            : "=r"(done) : "r"(mbar), "r"(parity) : "memory");
        if (done) return;
    }
}
// arrive on the LEADER CTA's barrier (bit 24 of cluster-mapped addr cleared)
__device__ __forceinline__ void mbar_arrive_leader(uint32_t mbar) {
    uint32_t la = mbar & 0xFEFFFFFFu;
    asm volatile("mbarrier.arrive.shared::cluster.b64 _, [%0];" :: "r"(la) : "memory");
}
// cg2 TMA: data to this CTA's SMEM; complete_tx to LEADER's barrier
__device__ __forceinline__ void tma_load_2d_cg2(uint32_t smem_dst, const CUtensorMap* map,
                                                int32_t cx, int32_t cy, uint32_t mbar) {
    uint32_t lb = mbar & 0xFEFFFFFFu;
    asm volatile(
        "cp.async.bulk.tensor.2d.cta_group::2.shared::cluster.global.tile.mbarrier::complete_tx::bytes "
        "[%0], [%1, {%2, %3}], [%4];"
        :: "r"(smem_dst), "l"(map), "r"(cx), "r"(cy), "r"(lb) : "memory");
}
// SW128 K-major smem descriptor (layout=2, version=1, SBO=64, LBO=1)
__device__ __forceinline__ uint64_t make_desc(uint32_t addr) {
    const uint64_t base = (uint64_t(2) << 61) | (uint64_t(1) << 46) |
                          (uint64_t(64) << 32) | (uint64_t(1) << 16);
    return base | ((uint64_t)(addr >> 4) & 0x3FFF);
}
__device__ __forceinline__ void mma_f16_ss_cg2(uint32_t d_tmem, uint64_t a_desc, uint64_t b_desc,
                                               uint32_t idesc, uint32_t enable) {
    asm volatile(
        "{\n\t.reg .pred p;\n\t"
        "setp.ne.u32 p, %5, 0;\n\t"
        "tcgen05.mma.cta_group::2.kind::f16 [%0], %1, %2, %3, "
        "{%4, %4, %4, %4, %4, %4, %4, %4}, p;\n\t}"
        :: "r"(d_tmem), "l"(a_desc), "l"(b_desc), "r"(idesc), "r"(0u), "r"(enable) : "memory");
}
__device__ __forceinline__ void tc_commit_mc2(uint32_t mbar) {
    asm volatile(
        "tcgen05.commit.cta_group::2.mbarrier::arrive::one.shared::cluster.multicast::cluster.b64 [%0], %1;"
        :: "r"(mbar), "h"((uint16_t)0x3) : "memory");
}

#define TC_ALLOC_CG2(slot, n)  asm volatile("tcgen05.alloc.cta_group::2.sync.aligned.shared::cta.b32 [%0], %1;" :: "r"(slot), "r"((uint32_t)(n)) : "memory")
#define TC_RELINQ_CG2()        asm volatile("tcgen05.relinquish_alloc_permit.cta_group::2.sync.aligned;")
#define TC_DEALLOC_CG2(t, n)   asm volatile("tcgen05.dealloc.cta_group::2.sync.aligned.b32 %0, %1;" :: "r"(t), "r"((uint32_t)(n)))
#define TC_WAIT_LD()       asm volatile("tcgen05.wait::ld.sync.aligned;" ::: "memory")
#define TC_FENCE_AFTER()   asm volatile("tcgen05.fence::after_thread_sync;" ::: "memory")
#define TC_FENCE_BEFORE()  asm volatile("tcgen05.fence::before_thread_sync;" ::: "memory")

#define LDTM_X32(r, addr) \
    asm volatile( \
        "tcgen05.ld.sync.aligned.32x32b.x32.b32 " \
        "{%0, %1, %2, %3, %4, %5, %6, %7, " \
        " %8, %9, %10, %11, %12, %13, %14, %15, " \
        " %16, %17, %18, %19, %20, %21, %22, %23, " \
        " %24, %25, %26, %27, %28, %29, %30, %31}, [%32];" \
        : "=r"((r)[0]),  "=r"((r)[1]),  "=r"((r)[2]),  "=r"((r)[3]), \
          "=r"((r)[4]),  "=r"((r)[5]),  "=r"((r)[6]),  "=r"((r)[7]), \
          "=r"((r)[8]),  "=r"((r)[9]),  "=r"((r)[10]), "=r"((r)[11]), \
          "=r"((r)[12]), "=r"((r)[13]), "=r"((r)[14]), "=r"((r)[15]), \
          "=r"((r)[16]), "=r"((r)[17]), "=r"((r)[18]), "=r"((r)[19]), \
          "=r"((r)[20]), "=r"((r)[21]), "=r"((r)[22]), "=r"((r)[23]), \
          "=r"((r)[24]), "=r"((r)[25]), "=r"((r)[26]), "=r"((r)[27]), \
          "=r"((r)[28]), "=r"((r)[29]), "=r"((r)[30]), "=r"((r)[31]) \
        : "r"(addr))
#endif  // HAS_TCGEN05

// ------------------------------- GEMM kernel ------------------------------
// Persistent: NPAIRS pairs each process tiles t = pairId, pairId+NPAIRS, ...
// Pair tile: C[256,256] = A[256,K] . W[256,K]^T, fp32 acc in TMEM (fp16 ops).
// Double-buffered accumulators (cols 0-255 / 256-511) let the epilogue of
// tile j overlap the mainloop of tile j+1.
// mode 0:        outH = fp16(tanh(C + bias))                          (GEMM1)
// mode 1,!last:  v = C + bias; acc' = first? v : acc + wcoef*v;
//                xe = fp16(x + ccn*v)                                 (GEMM2 e0..2)
// mode 1, last:  v = C + bias; xn = x + s6*(acc + v); x = xn; xe = fp16(xn)
__global__ void __launch_bounds__(256, 1) __cluster_dims__(2, 1, 1) gemm_kernel(
    const __grid_constant__ CUtensorMap tmA,
    const __grid_constant__ CUtensorMap tmB,
    int nchunks, int ntiles,
    const float* __restrict__ bias,
    int mode,
    __half* __restrict__ outH,
    float* __restrict__ outAcc,
    float* __restrict__ xcur,
    __half* __restrict__ xeout,
    float wcoef, int first, int last, float s6, float ccn, int nout,
    const __half* __restrict__ Araw,
    const float* __restrict__ Wraw)
{
#if HAS_TCGEN05
    extern __shared__ char smem[];
    uint32_t sbase = smem_u32(smem);
    uint32_t tile0 = (sbase + 1023u) & ~1023u;
    uint32_t ctrl  = tile0 + STAGES * CHUNK_BYTES;
    uint32_t mb_full    = ctrl;          // STAGES * 8B (leader-used)
    uint32_t mb_empty   = ctrl + 64;     // STAGES * 8B (both CTAs)
    uint32_t mb_accfull = ctrl + 128;    // 2 * 8B (both CTAs)
    uint32_t mb_accfree = ctrl + 160;    // 2 * 8B (leader waited, count 2)
    uint32_t tmem_slot  = ctrl + 192;

    const int tid = threadIdx.x, wid = tid >> 5, lane = tid & 31;
    const uint32_t rank = ctarank();
    const int pairId = (int)(blockIdx.x >> 1);
    const int npairs = (int)(gridDim.x >> 1);

    if (wid == 0) { TC_ALLOC_CG2(tmem_slot, 512); }
    if (tid == 0) {
        for (int s = 0; s < STAGES; s++) {
            mbar_init(mb_full  + 8*s, 1);
            mbar_init(mb_empty + 8*s, 1);
        }
        mbar_init(mb_accfull + 0, 1);  mbar_init(mb_accfull + 8, 1);
        mbar_init(mb_accfree + 0, 2);  mbar_init(mb_accfree + 8, 2);
    }
    __syncthreads();
    cluster_sync();   // peer barriers live before any cg2 TMA / multicast commit

    uint32_t tmem;
    asm volatile("ld.shared.b32 %0, [%1];" : "=r"(tmem) : "r"(tmem_slot));

    // ---- producer: warp 4 lane 0, BOTH CTAs ----
    if (wid == 4 && lane == 0) {
        int s = 0; uint32_t ph = 1;
        for (int t = pairId; t < ntiles; t += npairs) {
            const int mi = t & (MT - 1), ni = t >> 4;
            const int mself = mi * BMP + (int)rank * 128;
            const int nself = ni * BNP + (int)rank * 128;
            for (int c = 0; c < nchunks; c++) {
                mbar_wait(mb_empty + 8*s, ph);
                uint32_t st = tile0 + s * CHUNK_BYTES;
                if (rank == 0) mbar_expect_tx(mb_full + 8*s, PAIR_CHUNK_BYTES);
                tma_load_2d_cg2(st,              &tmA, c*BK, mself, mb_full + 8*s);
                tma_load_2d_cg2(st + TILE_BYTES, &tmB, c*BK, nself, mb_full + 8*s);
                if (++s == STAGES) { s = 0; ph ^= 1; }
            }
        }
    }

    // ---- MMA issuer: warp 5 lane 0, LEADER only ----
    if (rank == 0 && wid == 5 && lane == 0) {
        int s = 0; uint32_t ph = 0;
        int j = 0;
        for (int t = pairId; t < ntiles; t += npairs, j++) {
            const uint32_t b = (uint32_t)(j & 1);
            const uint32_t dtm = tmem + b * 256;
            if (j >= 2) { mbar_wait(mb_accfree + 8*b, (uint32_t)(((j - 2) >> 1) & 1)); TC_FENCE_AFTER(); }
            uint32_t en = 0;
            for (int c = 0; c < nchunks; c++) {
                mbar_wait(mb_full + 8*s, ph);
                uint32_t st = tile0 + s * CHUNK_BYTES;
                uint64_t da = make_desc(st);
                uint64_t db = make_desc(st + TILE_BYTES);
                #pragma unroll
                for (int k = 0; k < 4; k++) { mma_f16_ss_cg2(dtm, da + 2*k, db + 2*k, IDESC_CG2, en); en = 1; }
                tc_commit_mc2(mb_empty + 8*s);
                if (++s == STAGES) { s = 0; ph ^= 1; }
            }
            tc_commit_mc2(mb_accfull + 8*b);
        }
    }

    // ---- epilogue: warps 0-3, BOTH CTAs ----
    if (wid < 4) {
        int j = 0;
        for (int t = pairId; t < ntiles; t += npairs, j++) {
            const uint32_t b = (uint32_t)(j & 1);
            mbar_wait(mb_accfull + 8*b, (uint32_t)((j >> 1) & 1));
            TC_FENCE_AFTER();
            const int mi = t & (MT - 1), ni = t >> 4;
            const int m  = mi * BMP + (int)rank * 128 + wid * 32 + lane;
            const int n0 = ni * BNP;
            for (int nb = 0; nb < 8; nb++) {
                uint32_t rh[32];
                LDTM_X32(rh, tmem + b * 256 + nb * 32);
                TC_WAIT_LD();
                const int nc = n0 + nb * 32;
                if (mode == 0) {
                    uint32_t packed[16];
                    #pragma unroll
                    for (int q = 0; q < 16; q++) {
                        float v0 = __uint_as_float(rh[2*q])   + bias[nc + 2*q];
                        float v1 = __uint_as_float(rh[2*q+1]) + bias[nc + 2*q+1];
                        __half2 h2 = __floats2half2_rn(tanh_fast(v0), tanh_fast(v1));
                        packed[q] = *reinterpret_cast<uint32_t*>(&h2);
                    }
                    uint4* dst = reinterpret_cast<uint4*>(outH + (size_t)m * nout + nc);
                    #pragma unroll
                    for (int q = 0; q < 4; q++) dst[q] = reinterpret_cast<uint4*>(packed)[q];
                } else {
                    float vals[32];
                    #pragma unroll
                    for (int q = 0; q < 32; q++)
                        vals[q] = __uint_as_float(rh[q]) + bias[nc + q];
                    const size_t off = (size_t)m * nout + nc;
                    uint32_t packed[16];
                    if (!last) {
                        float4* da = reinterpret_cast<float4*>(outAcc + off);
                        const float4* dx = reinterpret_cast<const float4*>(xcur + off);
                        #pragma unroll
                        for (int q = 0; q < 8; q++) {
                            float4 v = reinterpret_cast<float4*>(vals)[q];
                            float4 a;
                            if (first) { a = v; }
                            else {
                                a = da[q];
                                a.x += wcoef * v.x; a.y += wcoef * v.y;
                                a.z += wcoef * v.z; a.w += wcoef * v.w;
                            }
                            da[q] = a;
                            float4 xo = dx[q];
                            __half2 h0 = __floats2half2_rn(fmaf(ccn, v.x, xo.x), fmaf(ccn, v.y, xo.y));
                            __half2 h1 = __floats2half2_rn(fmaf(ccn, v.z, xo.z), fmaf(ccn, v.w, xo.w));
                            packed[2*q]   = *reinterpret_cast<uint32_t*>(&h0);
                            packed[2*q+1] = *reinterpret_cast<uint32_t*>(&h1);
                        }
                    } else {
                        const float4* da = reinterpret_cast<const float4*>(outAcc + off);
                        float4* dx = reinterpret_cast<float4*>(xcur + off);
                        #pragma unroll
                        for (int q = 0; q < 8; q++) {
                            float4 v = reinterpret_cast<float4*>(vals)[q];
                            float4 a = da[q];
                            float4 xo = dx[q];
                            float4 xn;
                            xn.x = fmaf(s6, a.x + v.x, xo.x);
                            xn.y = fmaf(s6, a.y + v.y, xo.y);
                            xn.z = fmaf(s6, a.z + v.z, xo.z);
                            xn.w = fmaf(s6, a.w + v.w, xo.w);
                            dx[q] = xn;
                            __half2 h0 = __floats2half2_rn(xn.x, xn.y);
                            __half2 h1 = __floats2half2_rn(xn.z, xn.w);
                            packed[2*q]   = *reinterpret_cast<uint32_t*>(&h0);
                            packed[2*q+1] = *reinterpret_cast<uint32_t*>(&h1);
                        }
                    }
                    uint4* de = reinterpret_cast<uint4*>(xeout + off);
                    #pragma unroll
                    for (int q = 0; q < 4; q++) de[q] = reinterpret_cast<uint4*>(packed)[q];
                }
            }
            // release accumulator buffer b (both CTAs' 128 epilogue threads)
            TC_FENCE_BEFORE();
            asm volatile("bar.sync 1, 128;" ::: "memory");
            if (wid == 0 && lane == 0) mbar_arrive_leader(mb_accfree + 8*b);
        }
    }

    __syncthreads();
    if (wid == 0) { TC_RELINQ_CG2(); TC_DEALLOC_CG2(tmem, 512); }
    cluster_sync();

#else  // ---------------- fallback: fp32 FFMA tiled GEMM (plain sm_103) ----
    extern __shared__ char smem[];
    float* As = reinterpret_cast<float*>(smem);          // [16][128] k-major
    float* Bs = reinterpret_cast<float*>(smem + 8192);   // [16][128]

    const int K = nchunks * BK;
    const int tid = threadIdx.x;
    const int pairId = (int)(blockIdx.x >> 1);
    const int npairs = (int)(gridDim.x >> 1);
    const int rk = (int)(blockIdx.x & 1);
    const int tx = tid & 15, ty = tid >> 4;
    const int lr = tid >> 1;
    const int lc = (tid & 1) * 8;

    for (int t = pairId; t < ntiles; t += npairs) {
        const int mi = t & (MT - 1), ni = t >> 4;
        const int m0 = mi * BMP + rk * 128;
        for (int half = 0; half < 2; half++) {
            const int n0 = ni * BNP + half * 128;
            float acc[8][8];
            #pragma unroll
            for (int i = 0; i < 8; i++)
                #pragma unroll
                for (int jq = 0; jq < 8; jq++) acc[i][jq] = 0.0f;

            for (int k0 = 0; k0 < K; k0 += 16) {
                {
                    uint4 v = *reinterpret_cast<const uint4*>(Araw + (size_t)(m0 + lr) * K + k0 + lc);
                    const __half* hp = reinterpret_cast<const __half*>(&v);
                    #pragma unroll
                    for (int jq = 0; jq < 8; jq++) As[(lc + jq) * 128 + lr] = __half2float(hp[jq]);
                }
                {
                    const float* src = Wraw + (size_t)(n0 + lr) * K + k0 + lc;
                    float4 v1 = reinterpret_cast<const float4*>(src)[0];
                    float4 v2 = reinterpret_cast<const float4*>(src)[1];
                    Bs[(lc + 0) * 128 + lr] = v1.x; Bs[(lc + 1) * 128 + lr] = v1.y;
                    Bs[(lc + 2) * 128 + lr] = v1.z; Bs[(lc + 3) * 128 + lr] = v1.w;
                    Bs[(lc + 4) * 128 + lr] = v2.x; Bs[(lc + 5) * 128 + lr] = v2.y;
                    Bs[(lc + 6) * 128 + lr] = v2.z; Bs[(lc + 7) * 128 + lr] = v2.w;
                }
                __syncthreads();
                #pragma unroll
                for (int kk = 0; kk < 16; kk++) {
                    float a[8], bb[8];
                    #pragma unroll
                    for (int i = 0; i < 8; i++) a[i] = As[kk * 128 + ty * 8 + i];
                    #pragma unroll
                    for (int jq = 0; jq < 8; jq++) bb[jq] = Bs[kk * 128 + tx * 8 + jq];
                    #pragma unroll
                    for (int i = 0; i < 8; i++)
                        #pragma unroll
                        for (int jq = 0; jq < 8; jq++) acc[i][jq] = fmaf(a[i], bb[jq], acc[i][jq]);
                }
                __syncthreads();
            }

            #pragma unroll
            for (int i = 0; i < 8; i++) {
                int m = m0 + ty * 8 + i;
                #pragma unroll
                for (int jq = 0; jq < 8; jq++) {
                    int n = n0 + tx * 8 + jq;
                    float v = acc[i][jq] + bias[n];
                    size_t o = (size_t)m * nout + n;
                    if (mode == 0) {
                        outH[o] = __float2half_rn(tanh_fast(v));
                    } else if (!last) {
                        float a = first ? v : fmaf(wcoef, v, outAcc[o]);
                        outAcc[o] = a;
                        xeout[o] = __float2half_rn(fmaf(ccn, v, xcur[o]));
                    } else {
                        float xn = fmaf(s6, outAcc[o] + v, xcur[o]);
                        xcur[o] = xn;
                        xeout[o] = __float2half_rn(xn);
                    }
                }
            }
            __syncthreads();
        }
    }
#endif
}

// --------------------------- elementwise kernels --------------------------
__global__ void wconv_kernel(const float* __restrict__ W, __half* __restrict__ Wh, int n)
{
    int i = blockIdx.x * blockDim.x + threadIdx.x;
    if (i < n) Wh[i] = __float2half_rn(W[i]);
}

__global__ void prep_kernel(const float* __restrict__ xc, __half* __restrict__ xe, int n)
{
    int i = blockIdx.x * blockDim.x + threadIdx.x;
    if (i < n) xe[i] = __float2half_rn(xc[i]);
}

// ------------------------------- host side --------------------------------
typedef CUresult (*EncodeTiledFn)(
    CUtensorMap*, CUtensorMapDataType, cuuint32_t, void*,
    const cuuint64_t*, const cuuint64_t*, const cuuint32_t*, const cuuint32_t*,
    CUtensorMapInterleave, CUtensorMapSwizzle, CUtensorMapL2promotion, CUtensorMapFloatOOBfill);

static void encode_2d_f16(EncodeTiledFn fn, CUtensorMap* m, void* ptr,
                          uint64_t d0, uint64_t d1)
{
    if (!fn) return;
    cuuint64_t dims[2]    = {d0, d1};
    cuuint64_t strides[1] = {d0 * 2};
    cuuint32_t box[2]     = {BK, 128};          // 128 B x 128 rows
    cuuint32_t es[2]      = {1, 1};
    fn(m, CU_TENSOR_MAP_DATA_TYPE_FLOAT16, 2, ptr, dims, strides, box, es,
       CU_TENSOR_MAP_INTERLEAVE_NONE, CU_TENSOR_MAP_SWIZZLE_128B,
       CU_TENSOR_MAP_L2_PROMOTION_L2_128B, CU_TENSOR_MAP_FLOAT_OOB_FILL_NONE);
}

extern "C" void kernel_launch(void* const* d_in, const int* in_sizes, int n_in,
                              void* d_out, int out_size)
{
    const float* x  = (const float*)d_in[0];
    const float* W1 = (const float*)d_in[1];
    const float* b1 = (const float*)d_in[2];
    const float* W2 = (const float*)d_in[3];
    const float* b2 = (const float*)d_in[4];
    float* xc = (float*)d_out;                      // ODE state lives in d_out

    void *pW1h, *pW2h, *pxe, *ph, *pacc;
    cudaGetSymbolAddress(&pW1h, g_W1h);
    cudaGetSymbolAddress(&pW2h, g_W2h);
    cudaGetSymbolAddress(&pxe,  g_xe);
    cudaGetSymbolAddress(&ph,   g_h);
    cudaGetSymbolAddress(&pacc, g_acc);

    EncodeTiledFn encode_fn = nullptr;
    cudaDriverEntryPointQueryResult qres;
    cudaGetDriverEntryPoint("cuTensorMapEncodeTiled", (void**)&encode_fn,
                            cudaEnableDefault, &qres);

    cudaFuncSetAttribute(gemm_kernel, cudaFuncAttributeMaxDynamicSharedMemorySize, SMEM_REQ);

    alignas(64) CUtensorMap tmA1, tmB1, tmA2, tmB2;
    memset(&tmA1, 0, sizeof(tmA1)); memset(&tmB1, 0, sizeof(tmB1));
    memset(&tmA2, 0, sizeof(tmA2)); memset(&tmB2, 0, sizeof(tmB2));
    encode_2d_f16(encode_fn, &tmA1, pxe,  DD, BB);   // xe  [4096 x 1024]
    encode_2d_f16(encode_fn, &tmB1, pW1h, DD, HH);   // W1h [4096 x 1024]
    encode_2d_f16(encode_fn, &tmA2, ph,   HH, BB);   // h   [4096 x 4096]
    encode_2d_f16(encode_fn, &tmB2, pW2h, HH, DD);   // W2h [1024 x 4096]

    const int nelem = BB * DD;
    const int EB = 256;

    // init state + fp16 state + weight conversion (deterministic per call)
    cudaMemcpyAsync(xc, x, (size_t)nelem * sizeof(float), cudaMemcpyDeviceToDevice);
    prep_kernel<<<(nelem + EB - 1)/EB, EB>>>(xc, (__half*)pxe, nelem);
    wconv_kernel<<<(HH*DD + EB - 1)/EB, EB>>>(W1, (__half*)pW1h, HH*DD);
    wconv_kernel<<<(DD*HH + EB - 1)/EB, EB>>>(W2, (__half*)pW2h, DD*HH);

    const float dt = 1.0f / (float)NSTEPS;
    const float s6 = dt / 6.0f;
    const float csn[4] = {0.5f*dt, 0.5f*dt, dt, 0.0f};  // c for NEXT eval's xe
    const float ws[4]  = {1.0f, 2.0f, 2.0f, 1.0f};

    const int GRID = 2 * NPAIRS;  // 128 CTAs (64 cg2 pairs)

    for (int s = 0; s < NSTEPS; s++) {
        for (int e = 0; e < 4; e++) {
            // GEMM1: h = tanh(xe @ W1^T + b1)     256 tiles, 16 chunks
            gemm_kernel<<<GRID, 256, SMEM_REQ>>>(
                tmA1, tmB1, DD/BK, (BB/BMP)*(HH/BNP), b1, 0,
                (__half*)ph, nullptr, nullptr, nullptr,
                0.0f, 0, 0, 0.0f, 0.0f, HH,
                (const __half*)pxe, W1);
            // GEMM2: k = h @ W2^T + b2 ; RK4 accumulate + next xe (fused)
            gemm_kernel<<<GRID, 256, SMEM_REQ>>>(
                tmA2, tmB2, HH/BK, (BB/BMP)*(DD/BNP), b2, 1,
                nullptr, (float*)pacc, xc, (__half*)pxe,
                ws[e], (e == 0) ? 1 : 0, (e == 3) ? 1 : 0, s6, csn[e], DD,
                (const __half*)ph, W2);
        }
    }
    (void)in_sizes; (void)n_in; (void)out_size;
}

// round 12
// speedup vs baseline: 3.4268x; 2.4335x over previous
#include <cuda_runtime.h>
#include <cuda.h>
#include <cuda_fp16.h>
#include <cstdint>
#include <cstddef>
#include <cstring>

// ----------------------------- problem sizes ------------------------------
#define BB 4096   // batch
#define DD 1024   // input dim
#define HH 4096   // hidden dim
#define NSTEPS 64
#define NPH (NSTEPS*8)        // 512 phases: (step, eval, gemm1|gemm2)

// ------------------------------ GEMM tiling -------------------------------
#define BMP 256               // pair M (128 rows per CTA)
#define BNP 256               // pair N (128 B-rows per CTA)
#define BK 64                 // fp16 per K-chunk = 128 B (SW128 atom)
#define STAGES 6
#define TILE_BYTES 16384      // 128 rows * 128 B
#define CHUNK_BYTES (2*TILE_BYTES)        // per-CTA: A(16K) + B(16K)
#define PAIR_CHUNK_BYTES (2*CHUNK_BYTES)
#define SMEM_REQ (STAGES*CHUNK_BYTES + 2048)
#define NPAIRS 64
#define GRIDC (2*NPAIRS)      // 128 CTAs
#define MT 16                 // M pair-tiles = BB/BMP

#define G1_NCH (DD/BK)        // 16
#define G1_NT  ((BB/BMP)*(HH/BNP))  // 256
#define G2_NCH (HH/BK)        // 64
#define G2_NT  ((BB/BMP)*(DD/BNP))  // 64

// idesc kind::f16 cg2: dtype=F32(1<<4), a/btype=F16, N=256, M=256
#define IDESC_CG2 ((1u<<4) | (32u<<17) | (16u<<24))

#if defined(__CUDA_ARCH__) && (defined(__CUDA_ARCH_FEAT_SM103_ALL) || defined(__CUDA_ARCH_FEAT_SM100_ALL) || defined(__CUDA_ARCH_FEAT_SM101_ALL))
#define HAS_TCGEN05 1
#else
#define HAS_TCGEN05 0
#endif

// --------------------------- persistent scratch ---------------------------
__device__ __align__(1024) __half g_W1h[(size_t)HH * DD];
__device__ __align__(1024) __half g_W2h[(size_t)DD * HH];
__device__ __align__(1024) __half g_xe [(size_t)BB * DD];
__device__ __align__(1024) __half g_h  [(size_t)BB * HH];
__device__ __align__(1024) float  g_acc[(size_t)BB * DD];
__device__ unsigned int g_bar[NPH];

__device__ __forceinline__ float tanh_fast(float x) {
    float y; asm("tanh.approx.f32 %0, %1;" : "=f"(y) : "f"(x)); return y;
}

// device-wide barrier: one fresh counter per phase (no sense reversal needed)
__device__ __forceinline__ void grid_barrier(int phase) {
    __syncthreads();
    if (threadIdx.x == 0) {
        __threadfence();
#if HAS_TCGEN05
        asm volatile("fence.proxy.async;" ::: "memory");
#endif
        unsigned int* c = &g_bar[phase];
        atomicAdd(c, 1u);
        for (int i = 0; i < 2000000; i++) {
            unsigned int v;
            asm volatile("ld.acquire.gpu.u32 %0, [%1];" : "=r"(v) : "l"(c));
            if (v >= (unsigned)GRIDC) break;
        }
    }
    __syncthreads();
}

#if HAS_TCGEN05
// ------------------------------ PTX helpers -------------------------------
__device__ __forceinline__ uint32_t smem_u32(const void* p) {
    uint32_t a;
    asm("{ .reg .u64 t; cvta.to.shared.u64 t, %1; cvt.u32.u64 %0, t; }" : "=r"(a) : "l"(p));
    return a;
}
__device__ __forceinline__ uint32_t ctarank() {
    uint32_t r; asm("mov.u32 %0, %%cluster_ctarank;" : "=r"(r)); return r;
}
__device__ __forceinline__ void cluster_sync() {
    asm volatile("barrier.cluster.arrive.aligned;" ::: "memory");
    asm volatile("barrier.cluster.wait.aligned;" ::: "memory");
}
__device__ __forceinline__ void mbar_init(uint32_t mbar, uint32_t count) {
    asm volatile("mbarrier.init.shared.b64 [%0], %1;" :: "r"(mbar), "r"(count) : "memory");
}
__device__ __forceinline__ void mbar_expect_tx(uint32_t mbar, uint32_t bytes) {
    asm volatile("mbarrier.arrive.expect_tx.shared.b64 _, [%0], %1;" :: "r"(mbar), "r"(bytes) : "memory");
}
__device__ __forceinline__ void mbar_wait(uint32_t mbar, uint32_t parity) {
    for (int i = 0; i < 4000000; i++) {
        uint32_t done;
        asm volatile(
            "{\n\t.reg .pred P;\n\t"
            "mbarrier.try_wait.parity.acquire.cta.shared::cta.b64 P, [%1], %2;\n\t"
            "selp.b32 %0, 1, 0, P;\n\t}"
            : "=r"(done) : "r"(mbar), "r"(parity) : "memory");
        if (done) return;
    }
}
__device__ __forceinline__ void mbar_arrive_leader(uint32_t mbar) {
    uint32_t la = mbar & 0xFEFFFFFFu;
    asm volatile("mbarrier.arrive.shared::cluster.b64 _, [%0];" :: "r"(la) : "memory");
}
__device__ __forceinline__ void tma_load_2d_cg2(uint32_t smem_dst, const CUtensorMap* map,
                                                int32_t cx, int32_t cy, uint32_t mbar) {
    uint32_t lb = mbar & 0xFEFFFFFFu;
    asm volatile(
        "cp.async.bulk.tensor.2d.cta_group::2.shared::cluster.global.tile.mbarrier::complete_tx::bytes "
        "[%0], [%1, {%2, %3}], [%4];"
        :: "r"(smem_dst), "l"(map), "r"(cx), "r"(cy), "r"(lb) : "memory");
}
__device__ __forceinline__ uint64_t make_desc(uint32_t addr) {
    const uint64_t base = (uint64_t(2) << 61) | (uint64_t(1) << 46) |
                          (uint64_t(64) << 32) | (uint64_t(1) << 16);
    return base | ((uint64_t)(addr >> 4) & 0x3FFF);
}
__device__ __forceinline__ void mma_f16_ss_cg2(uint32_t d_tmem, uint64_t a_desc, uint64_t b_desc,
                                               uint32_t idesc, uint32_t enable) {
    asm volatile(
        "{\n\t.reg .pred p;\n\t"
        "setp.ne.u32 p, %5, 0;\n\t"
        "tcgen05.mma.cta_group::2.kind::f16 [%0], %1, %2, %3, "
        "{%4, %4, %4, %4, %4, %4, %4, %4}, p;\n\t}"
        :: "r"(d_tmem), "l"(a_desc), "l"(b_desc), "r"(idesc), "r"(0u), "r"(enable) : "memory");
}
__device__ __forceinline__ void tc_commit_mc2(uint32_t mbar) {
    asm volatile(
        "tcgen05.commit.cta_group::2.mbarrier::arrive::one.shared::cluster.multicast::cluster.b64 [%0], %1;"
        :: "r"(mbar), "h"((uint16_t)0x3) : "memory");
}

#define TC_ALLOC_CG2(slot, n)  asm volatile("tcgen05.alloc.cta_group::2.sync.aligned.shared::cta.b32 [%0], %1;" :: "r"(slot), "r"((uint32_t)(n)) : "memory")
#define TC_RELINQ_CG2()        asm volatile("tcgen05.relinquish_alloc_permit.cta_group::2.sync.aligned;")
#define TC_DEALLOC_CG2(t, n)   asm volatile("tcgen05.dealloc.cta_group::2.sync.aligned.b32 %0, %1;" :: "r"(t), "r"((uint32_t)(n)))
#define TC_WAIT_LD()       asm volatile("tcgen05.wait::ld.sync.aligned;" ::: "memory")
#define TC_FENCE_AFTER()   asm volatile("tcgen05.fence::after_thread_sync;" ::: "memory")
#define TC_FENCE_BEFORE()  asm volatile("tcgen05.fence::before_thread_sync;" ::: "memory")

#define LDTM_X32(r, addr) \
    asm volatile( \
        "tcgen05.ld.sync.aligned.32x32b.x32.b32 " \
        "{%0, %1, %2, %3, %4, %5, %6, %7, " \
        " %8, %9, %10, %11, %12, %13, %14, %15, " \
        " %16, %17, %18, %19, %20, %21, %22, %23, " \
        " %24, %25, %26, %27, %28, %29, %30, %31}, [%32];" \
        : "=r"((r)[0]),  "=r"((r)[1]),  "=r"((r)[2]),  "=r"((r)[3]), \
          "=r"((r)[4]),  "=r"((r)[5]),  "=r"((r)[6]),  "=r"((r)[7]), \
          "=r"((r)[8]),  "=r"((r)[9]),  "=r"((r)[10]), "=r"((r)[11]), \
          "=r"((r)[12]), "=r"((r)[13]), "=r"((r)[14]), "=r"((r)[15]), \
          "=r"((r)[16]), "=r"((r)[17]), "=r"((r)[18]), "=r"((r)[19]), \
          "=r"((r)[20]), "=r"((r)[21]), "=r"((r)[22]), "=r"((r)[23]), \
          "=r"((r)[24]), "=r"((r)[25]), "=r"((r)[26]), "=r"((r)[27]), \
          "=r"((r)[28]), "=r"((r)[29]), "=r"((r)[30]), "=r"((r)[31]) \
        : "r"(addr))
#endif  // HAS_TCGEN05

// ------------------------------- megakernel -------------------------------
// One launch runs all 64 RK4 steps. Phase p: step=p>>3, eval=(p>>1)&3,
// g2=p&1. Device-wide barrier between phases.
__global__ void __launch_bounds__(256, 1) __cluster_dims__(2, 1, 1) ode_mega_kernel(
    const __grid_constant__ CUtensorMap tmA1,
    const __grid_constant__ CUtensorMap tmB1,
    const __grid_constant__ CUtensorMap tmA2,
    const __grid_constant__ CUtensorMap tmB2,
    const float* __restrict__ b1,
    const float* __restrict__ b2,
    float* __restrict__ xc,
    const float* __restrict__ W1raw,
    const float* __restrict__ W2raw)
{
    const float dt = 1.0f / (float)NSTEPS;
    const float s6 = dt / 6.0f;

#if HAS_TCGEN05
    extern __shared__ char smem[];
    uint32_t sbase = smem_u32(smem);
    uint32_t tile0 = (sbase + 1023u) & ~1023u;
    uint32_t ctrl  = tile0 + STAGES * CHUNK_BYTES;
    uint32_t mb_full    = ctrl;          // STAGES * 8B
    uint32_t mb_empty   = ctrl + 64;     // STAGES * 8B
    uint32_t mb_accfull = ctrl + 128;    // 2 * 8B
    uint32_t mb_accfree = ctrl + 160;    // 2 * 8B (count 2)
    uint32_t tmem_slot  = ctrl + 192;

    const int tid = threadIdx.x, wid = tid >> 5, lane = tid & 31;
    const uint32_t rank = ctarank();
    const int pairId = (int)(blockIdx.x >> 1);

    if (wid == 0) { TC_ALLOC_CG2(tmem_slot, 512); }
    if (tid == 0) {
        for (int s = 0; s < STAGES; s++) {
            mbar_init(mb_full  + 8*s, 1);
            mbar_init(mb_empty + 8*s, 1);
        }
        mbar_init(mb_accfull + 0, 1);  mbar_init(mb_accfull + 8, 1);
        mbar_init(mb_accfree + 0, 2);  mbar_init(mb_accfree + 8, 2);
    }
    __syncthreads();
    cluster_sync();

    uint32_t tmem;
    asm volatile("ld.shared.b32 %0, [%1];" : "=r"(tmem) : "r"(tmem_slot));

    // persistent per-role state (flows across phases)
    int pr_s = 0;  uint32_t pr_ph = 1;   // producer stage/phase
    int mm_s = 0;  uint32_t mm_ph = 0;   // MMA stage/phase
    int mm_j = 0;                        // MMA global tile counter
    int ep_j = 0;                        // epilogue global tile counter

    for (int phase = 0; phase < NPH; phase++) {
        const int e  = (phase >> 1) & 3;
        const int g2 = phase & 1;
        const int nchunks = g2 ? G2_NCH : G1_NCH;
        const int ntiles  = g2 ? G2_NT  : G1_NT;
        const CUtensorMap* mA = g2 ? &tmA2 : &tmA1;
        const CUtensorMap* mB = g2 ? &tmB2 : &tmB1;
        const float* bias = g2 ? b2 : b1;
        const float wcoef = (e == 1 || e == 2) ? 2.0f : 1.0f;
        const float ccn   = (e == 0 || e == 1) ? 0.5f*dt : (e == 2 ? dt : 0.0f);
        const int first = (e == 0), last = (e == 3);
        const int nout = g2 ? DD : HH;

        // ---- producer: warp 4 lane 0, BOTH CTAs ----
        if (wid == 4 && lane == 0) {
            for (int t = pairId; t < ntiles; t += NPAIRS) {
                const int mi = t & (MT - 1), ni = t >> 4;
                const int mself = mi * BMP + (int)rank * 128;
                const int nself = ni * BNP + (int)rank * 128;
                for (int c = 0; c < nchunks; c++) {
                    mbar_wait(mb_empty + 8*pr_s, pr_ph);
                    uint32_t st = tile0 + pr_s * CHUNK_BYTES;
                    if (rank == 0) mbar_expect_tx(mb_full + 8*pr_s, PAIR_CHUNK_BYTES);
                    tma_load_2d_cg2(st,              mA, c*BK, mself, mb_full + 8*pr_s);
                    tma_load_2d_cg2(st + TILE_BYTES, mB, c*BK, nself, mb_full + 8*pr_s);
                    if (++pr_s == STAGES) { pr_s = 0; pr_ph ^= 1; }
                }
            }
        }

        // ---- MMA issuer: warp 5 lane 0, LEADER only ----
        if (rank == 0 && wid == 5 && lane == 0) {
            for (int t = pairId; t < ntiles; t += NPAIRS, mm_j++) {
                const uint32_t b = (uint32_t)(mm_j & 1);
                const uint32_t dtm = tmem + b * 256;
                if (mm_j >= 2) { mbar_wait(mb_accfree + 8*b, (uint32_t)(((mm_j - 2) >> 1) & 1)); TC_FENCE_AFTER(); }
                uint32_t en = 0;
                for (int c = 0; c < nchunks; c++) {
                    mbar_wait(mb_full + 8*mm_s, mm_ph);
                    uint32_t st = tile0 + mm_s * CHUNK_BYTES;
                    uint64_t da = make_desc(st);
                    uint64_t db = make_desc(st + TILE_BYTES);
                    #pragma unroll
                    for (int k = 0; k < 4; k++) { mma_f16_ss_cg2(dtm, da + 2*k, db + 2*k, IDESC_CG2, en); en = 1; }
                    tc_commit_mc2(mb_empty + 8*mm_s);
                    if (++mm_s == STAGES) { mm_s = 0; mm_ph ^= 1; }
                }
                tc_commit_mc2(mb_accfull + 8*b);
            }
        }

        // ---- epilogue: warps 0-3, BOTH CTAs ----
        if (wid < 4) {
            for (int t = pairId; t < ntiles; t += NPAIRS, ep_j++) {
                const uint32_t b = (uint32_t)(ep_j & 1);
                mbar_wait(mb_accfull + 8*b, (uint32_t)((ep_j >> 1) & 1));
                TC_FENCE_AFTER();
                const int mi = t & (MT - 1), ni = t >> 4;
                const int m  = mi * BMP + (int)rank * 128 + wid * 32 + lane;
                const int n0 = ni * BNP;
                for (int nb = 0; nb < 8; nb++) {
                    uint32_t rh[32];
                    LDTM_X32(rh, tmem + b * 256 + nb * 32);
                    TC_WAIT_LD();
                    const int nc = n0 + nb * 32;
                    if (!g2) {
                        uint32_t packed[16];
                        #pragma unroll
                        for (int q = 0; q < 16; q++) {
                            float v0 = __uint_as_float(rh[2*q])   + bias[nc + 2*q];
                            float v1 = __uint_as_float(rh[2*q+1]) + bias[nc + 2*q+1];
                            __half2 h2 = __floats2half2_rn(tanh_fast(v0), tanh_fast(v1));
                            packed[q] = *reinterpret_cast<uint32_t*>(&h2);
                        }
                        uint4* dst = reinterpret_cast<uint4*>(g_h + (size_t)m * nout + nc);
                        #pragma unroll
                        for (int q = 0; q < 4; q++) dst[q] = reinterpret_cast<uint4*>(packed)[q];
                    } else {
                        float vals[32];
                        #pragma unroll
                        for (int q = 0; q < 32; q++)
                            vals[q] = __uint_as_float(rh[q]) + bias[nc + q];
                        const size_t off = (size_t)m * nout + nc;
                        uint32_t packed[16];
                        if (!last) {
                            float4* da = reinterpret_cast<float4*>(g_acc + off);
                            const float4* dx = reinterpret_cast<const float4*>(xc + off);
                            #pragma unroll
                            for (int q = 0; q < 8; q++) {
                                float4 v = reinterpret_cast<float4*>(vals)[q];
                                float4 a;
                                if (first) { a = v; }
                                else {
                                    a = da[q];
                                    a.x += wcoef * v.x; a.y += wcoef * v.y;
                                    a.z += wcoef * v.z; a.w += wcoef * v.w;
                                }
                                da[q] = a;
                                float4 xo = dx[q];
                                __half2 h0 = __floats2half2_rn(fmaf(ccn, v.x, xo.x), fmaf(ccn, v.y, xo.y));
                                __half2 h1 = __floats2half2_rn(fmaf(ccn, v.z, xo.z), fmaf(ccn, v.w, xo.w));
                                packed[2*q]   = *reinterpret_cast<uint32_t*>(&h0);
                                packed[2*q+1] = *reinterpret_cast<uint32_t*>(&h1);
                            }
                        } else {
                            const float4* da = reinterpret_cast<const float4*>(g_acc + off);
                            float4* dx = reinterpret_cast<float4*>(xc + off);
                            #pragma unroll
                            for (int q = 0; q < 8; q++) {
                                float4 v = reinterpret_cast<float4*>(vals)[q];
                                float4 a = da[q];
                                float4 xo = dx[q];
                                float4 xn;
                                xn.x = fmaf(s6, a.x + v.x, xo.x);
                                xn.y = fmaf(s6, a.y + v.y, xo.y);
                                xn.z = fmaf(s6, a.z + v.z, xo.z);
                                xn.w = fmaf(s6, a.w + v.w, xo.w);
                                dx[q] = xn;
                                __half2 h0 = __floats2half2_rn(xn.x, xn.y);
                                __half2 h1 = __floats2half2_rn(xn.z, xn.w);
                                packed[2*q]   = *reinterpret_cast<uint32_t*>(&h0);
                                packed[2*q+1] = *reinterpret_cast<uint32_t*>(&h1);
                            }
                        }
                        uint4* de = reinterpret_cast<uint4*>(g_xe + off);
                        #pragma unroll
                        for (int q = 0; q < 4; q++) de[q] = reinterpret_cast<uint4*>(packed)[q];
                    }
                }
                TC_FENCE_BEFORE();
                asm volatile("bar.sync 1, 128;" ::: "memory");
                if (wid == 0 && lane == 0) mbar_arrive_leader(mb_accfree + 8*b);
            }
        }

        grid_barrier(phase);
    }

    if (wid == 0) { TC_RELINQ_CG2(); TC_DEALLOC_CG2(tmem, 512); }
    cluster_sync();

#else  // ---------------- fallback: fp32 FFMA phase loop (plain sm_103) ----
    extern __shared__ char smem[];
    float* As = reinterpret_cast<float*>(smem);
    float* Bs = reinterpret_cast<float*>(smem + 8192);

    const int tid = threadIdx.x;
    const int pairId = (int)(blockIdx.x >> 1);
    const int rk = (int)(blockIdx.x & 1);
    const int tx = tid & 15, ty = tid >> 4;
    const int lr = tid >> 1;
    const int lc = (tid & 1) * 8;

    for (int phase = 0; phase < NPH; phase++) {
        const int e  = (phase >> 1) & 3;
        const int g2 = phase & 1;
        const int K = g2 ? HH : DD;
        const int ntiles = g2 ? G2_NT : G1_NT;
        const __half* Araw = g2 ? g_h : g_xe;
        const float* Wraw = g2 ? W2raw : W1raw;
        const float* bias = g2 ? b2 : b1;
        const float wcoef = (e == 1 || e == 2) ? 2.0f : 1.0f;
        const float ccn   = (e == 0 || e == 1) ? 0.5f*dt : (e == 2 ? dt : 0.0f);
        const int first = (e == 0), last = (e == 3);
        const int nout = g2 ? DD : HH;

        for (int t = pairId; t < ntiles; t += NPAIRS) {
            const int mi = t & (MT - 1), ni = t >> 4;
            const int m0 = mi * BMP + rk * 128;
            for (int half = 0; half < 2; half++) {
                const int n0 = ni * BNP + half * 128;
                float acc[8][8];
                #pragma unroll
                for (int i = 0; i < 8; i++)
                    #pragma unroll
                    for (int jq = 0; jq < 8; jq++) acc[i][jq] = 0.0f;

                for (int k0 = 0; k0 < K; k0 += 16) {
                    {
                        uint4 v = *reinterpret_cast<const uint4*>(Araw + (size_t)(m0 + lr) * K + k0 + lc);
                        const __half* hp = reinterpret_cast<const __half*>(&v);
                        #pragma unroll
                        for (int jq = 0; jq < 8; jq++) As[(lc + jq) * 128 + lr] = __half2float(hp[jq]);
                    }
                    {
                        const float* src = Wraw + (size_t)(n0 + lr) * K + k0 + lc;
                        float4 v1 = reinterpret_cast<const float4*>(src)[0];
                        float4 v2 = reinterpret_cast<const float4*>(src)[1];
                        Bs[(lc + 0) * 128 + lr] = v1.x; Bs[(lc + 1) * 128 + lr] = v1.y;
                        Bs[(lc + 2) * 128 + lr] = v1.z; Bs[(lc + 3) * 128 + lr] = v1.w;
                        Bs[(lc + 4) * 128 + lr] = v2.x; Bs[(lc + 5) * 128 + lr] = v2.y;
                        Bs[(lc + 6) * 128 + lr] = v2.z; Bs[(lc + 7) * 128 + lr] = v2.w;
                    }
                    __syncthreads();
                    #pragma unroll
                    for (int kk = 0; kk < 16; kk++) {
                        float a[8], bb[8];
                        #pragma unroll
                        for (int i = 0; i < 8; i++) a[i] = As[kk * 128 + ty * 8 + i];
                        #pragma unroll
                        for (int jq = 0; jq < 8; jq++) bb[jq] = Bs[kk * 128 + tx * 8 + jq];
                        #pragma unroll
                        for (int i = 0; i < 8; i++)
                            #pragma unroll
                            for (int jq = 0; jq < 8; jq++) acc[i][jq] = fmaf(a[i], bb[jq], acc[i][jq]);
                    }
                    __syncthreads();
                }

                #pragma unroll
                for (int i = 0; i < 8; i++) {
                    int m = m0 + ty * 8 + i;
                    #pragma unroll
                    for (int jq = 0; jq < 8; jq++) {
                        int n = n0 + tx * 8 + jq;
                        float v = acc[i][jq] + bias[n];
                        size_t o = (size_t)m * nout + n;
                        if (!g2) {
                            g_h[o] = __float2half_rn(tanh_fast(v));
                        } else if (!last) {
                            float a = first ? v : fmaf(wcoef, v, g_acc[o]);
                            g_acc[o] = a;
                            g_xe[o] = __float2half_rn(fmaf(ccn, v, xc[o]));
                        } else {
                            float xn = fmaf(s6, g_acc[o] + v, xc[o]);
                            xc[o] = xn;
                            g_xe[o] = __float2half_rn(xn);
                        }
                    }
                }
                __syncthreads();
            }
        }
        grid_barrier(phase);
    }
#endif
}

// --------------------------- setup kernels --------------------------------
__global__ void wconv_kernel(const float* __restrict__ W, __half* __restrict__ Wh, int n)
{
    int i = blockIdx.x * blockDim.x + threadIdx.x;
    if (i < n) Wh[i] = __float2half_rn(W[i]);
}

__global__ void prep_kernel(const float* __restrict__ xcin, __half* __restrict__ xe, int n)
{
    int i = blockIdx.x * blockDim.x + threadIdx.x;
    if (i < n) xe[i] = __float2half_rn(xcin[i]);
}

__global__ void zero_bar_kernel()
{
    int i = blockIdx.x * blockDim.x + threadIdx.x;
    if (i < NPH) g_bar[i] = 0u;
}

// ------------------------------- host side --------------------------------
typedef CUresult (*EncodeTiledFn)(
    CUtensorMap*, CUtensorMapDataType, cuuint32_t, void*,
    const cuuint64_t*, const cuuint64_t*, const cuuint32_t*, const cuuint32_t*,
    CUtensorMapInterleave, CUtensorMapSwizzle, CUtensorMapL2promotion, CUtensorMapFloatOOBfill);

static void encode_2d_f16(EncodeTiledFn fn, CUtensorMap* m, void* ptr,
                          uint64_t d0, uint64_t d1)
{
    if (!fn) return;
    cuuint64_t dims[2]    = {d0, d1};
    cuuint64_t strides[1] = {d0 * 2};
    cuuint32_t box[2]     = {BK, 128};
    cuuint32_t es[2]      = {1, 1};
    fn(m, CU_TENSOR_MAP_DATA_TYPE_FLOAT16, 2, ptr, dims, strides, box, es,
       CU_TENSOR_MAP_INTERLEAVE_NONE, CU_TENSOR_MAP_SWIZZLE_128B,
       CU_TENSOR_MAP_L2_PROMOTION_L2_128B, CU_TENSOR_MAP_FLOAT_OOB_FILL_NONE);
}

extern "C" void kernel_launch(void* const* d_in, const int* in_sizes, int n_in,
                              void* d_out, int out_size)
{
    const float* x  = (const float*)d_in[0];
    const float* W1 = (const float*)d_in[1];
    const float* b1 = (const float*)d_in[2];
    const float* W2 = (const float*)d_in[3];
    const float* b2 = (const float*)d_in[4];
    float* xc = (float*)d_out;

    void *pW1h, *pW2h, *pxe, *ph;
    cudaGetSymbolAddress(&pW1h, g_W1h);
    cudaGetSymbolAddress(&pW2h, g_W2h);
    cudaGetSymbolAddress(&pxe,  g_xe);
    cudaGetSymbolAddress(&ph,   g_h);

    EncodeTiledFn encode_fn = nullptr;
    cudaDriverEntryPointQueryResult qres;
    cudaGetDriverEntryPoint("cuTensorMapEncodeTiled", (void**)&encode_fn,
                            cudaEnableDefault, &qres);

    cudaFuncSetAttribute(ode_mega_kernel, cudaFuncAttributeMaxDynamicSharedMemorySize, SMEM_REQ);

    alignas(64) CUtensorMap tmA1, tmB1, tmA2, tmB2;
    memset(&tmA1, 0, sizeof(tmA1)); memset(&tmB1, 0, sizeof(tmB1));
    memset(&tmA2, 0, sizeof(tmA2)); memset(&tmB2, 0, sizeof(tmB2));
    encode_2d_f16(encode_fn, &tmA1, pxe,  DD, BB);   // xe  [4096 x 1024]
    encode_2d_f16(encode_fn, &tmB1, pW1h, DD, HH);   // W1h [4096 x 1024]
    encode_2d_f16(encode_fn, &tmA2, ph,   HH, BB);   // h   [4096 x 4096]
    encode_2d_f16(encode_fn, &tmB2, pW2h, HH, DD);   // W2h [1024 x 4096]

    const int nelem = BB * DD;
    const int EB = 256;

    cudaMemcpyAsync(xc, x, (size_t)nelem * sizeof(float), cudaMemcpyDeviceToDevice);
    prep_kernel<<<(nelem + EB - 1)/EB, EB>>>(xc, (__half*)pxe, nelem);
    wconv_kernel<<<(HH*DD + EB - 1)/EB, EB>>>(W1, (__half*)pW1h, HH*DD);
    wconv_kernel<<<(DD*HH + EB - 1)/EB, EB>>>(W2, (__half*)pW2h, DD*HH);
    zero_bar_kernel<<<(NPH + EB - 1)/EB, EB>>>();

    ode_mega_kernel<<<GRIDC, 256, SMEM_REQ>>>(
        tmA1, tmB1, tmA2, tmB2, b1, b2, xc, W1, W2);

    (void)in_sizes; (void)n_in; (void)out_size;
}